// round 2
// baseline (speedup 1.0000x reference)
#include <cuda_runtime.h>
#include <cuda_bf16.h>

// Problem constants (from reference_code)
#define B      4096
#define DIN    1024
#define DOUT   1024
#define NEXP   8
#define BM     64
#define BN     64
#define BK     16
#define MAX_TILES 72   // sum_e ceil(n_e/64) <= 4096/64 + 8

// Scratch (device globals: no allocation allowed)
__device__ int g_perm[B];
__device__ int g_tile_expert[MAX_TILES];
__device__ int g_tile_row0[MAX_TILES];
__device__ int g_tile_rows[MAX_TILES];
__device__ int g_ntiles;

// ---------------------------------------------------------------------------
// Kernel 1: counting sort of actions -> permutation + single-expert row tiles
// actions arrive as int32 (harness downcasts int64).
// ---------------------------------------------------------------------------
__global__ void sort_kernel(const int* __restrict__ actions) {
    __shared__ int cnt[NEXP];
    __shared__ int offs[NEXP + 1];
    __shared__ int cur[NEXP];
    int tid = threadIdx.x;
    if (tid < NEXP) cnt[tid] = 0;
    __syncthreads();
    for (int i = tid; i < B; i += blockDim.x) {
        int e = actions[i] & (NEXP - 1);   // defensive clamp
        atomicAdd(&cnt[e], 1);
    }
    __syncthreads();
    if (tid == 0) {
        int s = 0;
        for (int e = 0; e < NEXP; e++) { offs[e] = s; s += cnt[e]; }
        offs[NEXP] = s;
        int nt = 0;
        for (int e = 0; e < NEXP; e++) {
            for (int r = offs[e]; r < offs[e + 1]; r += BM) {
                g_tile_expert[nt] = e;
                g_tile_row0[nt]   = r;
                g_tile_rows[nt]   = min(BM, offs[e + 1] - r);
                nt++;
            }
        }
        g_ntiles = nt;
        for (int e = 0; e < NEXP; e++) cur[e] = offs[e];
    }
    __syncthreads();
    for (int i = tid; i < B; i += blockDim.x) {
        int e = actions[i] & (NEXP - 1);
        int pos = atomicAdd(&cur[e], 1);
        g_perm[pos] = i;
    }
}

// ---------------------------------------------------------------------------
// Kernel 2: fp32 GEMM per single-expert tile.
//   C[rows(tile), n0:n0+64] = x[rows] @ W[e]^T + b[e]
//   W layout: [E][DOUT][DIN] row-major -> dot(x_row, W[e][n][:]).
// 256 threads, each computes 4x4 microtile. smem tiles As[16][64], Bs[16][64].
// ---------------------------------------------------------------------------
__global__ __launch_bounds__(256) void gemm_kernel(
    const float* __restrict__ x,
    const float* __restrict__ W,
    const float* __restrict__ bias,
    float* __restrict__ out)
{
    int t = blockIdx.x;
    if (t >= g_ntiles) return;
    const int e     = g_tile_expert[t];
    const int row0  = g_tile_row0[t];
    const int nrows = g_tile_rows[t];
    const int n0    = blockIdx.y * BN;

    __shared__ float As[BK][BM];
    __shared__ float Bs[BK][BN];
    __shared__ int   rows[BM];

    const int tid = threadIdx.x;
    if (tid < BM) rows[tid] = (tid < nrows) ? g_perm[row0 + tid] : -1;
    __syncthreads();

    const int lm = tid >> 2;   // 0..63: which row/col this thread loads
    const int lq = tid & 3;    // which 4-float chunk of the 16-wide k slab
    const int tx = tid & 15;   // output col group
    const int ty = tid >> 4;   // output row group

    const float* __restrict__ wbase = W + ((size_t)e * DOUT * DIN);
    const int myrow = rows[lm];
    const float* __restrict__ arow = (myrow >= 0) ? (x + (size_t)myrow * DIN) : x;
    const float* __restrict__ brow = wbase + (size_t)(n0 + lm) * DIN;

    float acc[4][4];
#pragma unroll
    for (int i = 0; i < 4; i++)
#pragma unroll
        for (int j = 0; j < 4; j++) acc[i][j] = 0.0f;

    for (int k0 = 0; k0 < DIN; k0 += BK) {
        float4 av = *(const float4*)(arow + k0 + lq * 4);
        if (myrow < 0) av = make_float4(0.f, 0.f, 0.f, 0.f);
        float4 bv = *(const float4*)(brow + k0 + lq * 4);
        __syncthreads();   // previous iteration's compute done
        As[lq * 4 + 0][lm] = av.x;
        As[lq * 4 + 1][lm] = av.y;
        As[lq * 4 + 2][lm] = av.z;
        As[lq * 4 + 3][lm] = av.w;
        Bs[lq * 4 + 0][lm] = bv.x;
        Bs[lq * 4 + 1][lm] = bv.y;
        Bs[lq * 4 + 2][lm] = bv.z;
        Bs[lq * 4 + 3][lm] = bv.w;
        __syncthreads();
#pragma unroll
        for (int kk = 0; kk < BK; kk++) {
            float4 a = *(const float4*)&As[kk][ty * 4];
            float4 b = *(const float4*)&Bs[kk][tx * 4];
            acc[0][0] += a.x * b.x; acc[0][1] += a.x * b.y;
            acc[0][2] += a.x * b.z; acc[0][3] += a.x * b.w;
            acc[1][0] += a.y * b.x; acc[1][1] += a.y * b.y;
            acc[1][2] += a.y * b.z; acc[1][3] += a.y * b.w;
            acc[2][0] += a.z * b.x; acc[2][1] += a.z * b.y;
            acc[2][2] += a.z * b.z; acc[2][3] += a.z * b.w;
            acc[3][0] += a.w * b.x; acc[3][1] += a.w * b.y;
            acc[3][2] += a.w * b.z; acc[3][3] += a.w * b.w;
        }
    }

    // epilogue: add bias, scatter to original row order
    const float* __restrict__ be = bias + e * DOUT + n0 + tx * 4;
    float4 bb = *(const float4*)be;
#pragma unroll
    for (int i = 0; i < 4; i++) {
        int m = ty * 4 + i;
        int r = rows[m];
        if (r < 0) continue;
        float4 v;
        v.x = acc[i][0] + bb.x;
        v.y = acc[i][1] + bb.y;
        v.z = acc[i][2] + bb.z;
        v.w = acc[i][3] + bb.w;
        *(float4*)(out + (size_t)r * DOUT + n0 + tx * 4) = v;
    }
}

// ---------------------------------------------------------------------------
// Kernel 3: passthrough tail (mxs, actions) appended after ys, if out_size
// indicates the harness packs the full tuple into one float buffer.
// ---------------------------------------------------------------------------
__global__ void tail_kernel(const int* __restrict__ mxs,
                            const int* __restrict__ actions,
                            float* __restrict__ out, int extra)
{
    int i = blockIdx.x * blockDim.x + threadIdx.x;
    if (i >= B) return;
    const size_t base = (size_t)B * DOUT;
    if (extra >= B)     out[base + i]     = (float)mxs[i];
    if (extra >= 2 * B) out[base + B + i] = (float)actions[i];
}

extern "C" void kernel_launch(void* const* d_in, const int* in_sizes, int n_in,
                              void* d_out, int out_size)
{
    const float* xs      = (const float*)d_in[0];
    const int*   mxs     = (const int*)d_in[1];
    const int*   actions = (const int*)d_in[2];
    const float* W       = (const float*)d_in[3];
    const float* bias    = (const float*)d_in[4];
    float*       out     = (float*)d_out;

    sort_kernel<<<1, 512>>>(actions);

    dim3 grid(MAX_TILES, DOUT / BN);
    gemm_kernel<<<grid, 256>>>(xs, W, bias, out);

    int extra = out_size - B * DOUT;
    if (extra > 0) {
        tail_kernel<<<(B + 255) / 256, 256>>>(mxs, actions, out, extra);
    }
}

// round 6
// speedup vs baseline: 2.6665x; 2.6665x over previous
#include <cuda_runtime.h>
#include <cuda_bf16.h>
#include <cstdint>

// ---------------------------------------------------------------------------
// Problem constants
// ---------------------------------------------------------------------------
#define B      4096
#define DIN    1024
#define DOUT   1024
#define NEXP   8
#define BM     128
#define BN     128
#define BK     32              // bf16 elems per k-chunk
#define NCHUNK (DIN / BK)      // 32
#define MAX_TILES 40

#define PAD       40           // smem row stride in bf16 elems (80B, conflict-free ldmatrix)
#define TILE_B    (BM * PAD * 2)       // 10240 bytes per sub-tile
#define T_AL      TILE_B
#define T_BH      (2 * TILE_B)
#define T_BL      (3 * TILE_B)
#define STAGE_B   (4 * TILE_B)         // 40960
#define SMEM_ROWS (2 * STAGE_B)        // 81920: rows_s
#define SMEM_BIAS (SMEM_ROWS + 512)    // bias_s
#define SMEM_TOTAL (SMEM_BIAS + 512)   // 82944

// ---------------------------------------------------------------------------
// Device-global scratch (allocation-free rule)
// ---------------------------------------------------------------------------
__device__ int g_perm[B];
__device__ int g_tile_expert[MAX_TILES];
__device__ int g_tile_row0[MAX_TILES];
__device__ int g_tile_rows[MAX_TILES];
__device__ int g_ntiles;
__device__ __align__(128) __nv_bfloat16 g_xh[B * DIN];
__device__ __align__(128) __nv_bfloat16 g_xl[B * DIN];
__device__ __align__(128) __nv_bfloat16 g_wh[NEXP * DOUT * DIN];
__device__ __align__(128) __nv_bfloat16 g_wl[NEXP * DOUT * DIN];

// ---------------------------------------------------------------------------
// PTX helpers (all baseline sm_80+ ISA — no sm_103a feature ops)
// ---------------------------------------------------------------------------
__device__ __forceinline__ uint32_t smem_to_u32(const void* p) {
    uint32_t a;
    asm("{ .reg .u64 t; cvta.to.shared.u64 t, %1; cvt.u32.u64 %0, t; }" : "=r"(a) : "l"(p));
    return a;
}
__device__ __forceinline__ void cpasync16(uint32_t dst, const void* src) {
    asm volatile("cp.async.cg.shared.global [%0], [%1], 16;" :: "r"(dst), "l"(src));
}
#define CP_COMMIT() asm volatile("cp.async.commit_group;" ::: "memory")
#define CP_WAIT(n)  asm volatile("cp.async.wait_group %0;" :: "n"(n) : "memory")

__device__ __forceinline__ void ldsm4(uint32_t* r, uint32_t addr) {
    asm volatile("ldmatrix.sync.aligned.m8n8.x4.shared.b16 {%0,%1,%2,%3}, [%4];"
        : "=r"(r[0]), "=r"(r[1]), "=r"(r[2]), "=r"(r[3]) : "r"(addr));
}
__device__ __forceinline__ void mma16816(float* c, const uint32_t* a, uint32_t b0, uint32_t b1) {
    asm volatile(
        "mma.sync.aligned.m16n8k16.row.col.f32.bf16.bf16.f32 "
        "{%0,%1,%2,%3}, {%4,%5,%6,%7}, {%8,%9}, {%0,%1,%2,%3};"
        : "+f"(c[0]), "+f"(c[1]), "+f"(c[2]), "+f"(c[3])
        : "r"(a[0]), "r"(a[1]), "r"(a[2]), "r"(a[3]), "r"(b0), "r"(b1));
}

// ---------------------------------------------------------------------------
// Kernel 1: warp-aggregated counting sort
// ---------------------------------------------------------------------------
__global__ void sort_kernel(const int* __restrict__ actions) {
    __shared__ int cnt[NEXP];
    __shared__ int offs[NEXP + 1];
    __shared__ int cur[NEXP];
    int tid = threadIdx.x;
    int lane = tid & 31;
    if (tid < NEXP) cnt[tid] = 0;
    __syncthreads();
    for (int i = tid; i < B; i += 1024) {
        int e = actions[i] & (NEXP - 1);
        unsigned m = __match_any_sync(0xFFFFFFFFu, e);
        if (lane == (__ffs(m) - 1)) atomicAdd(&cnt[e], __popc(m));
    }
    __syncthreads();
    if (tid == 0) {
        int s = 0;
        for (int e = 0; e < NEXP; e++) { offs[e] = s; s += cnt[e]; }
        offs[NEXP] = s;
        int nt = 0;
        for (int e = 0; e < NEXP; e++)
            for (int r = offs[e]; r < offs[e + 1]; r += BM) {
                g_tile_expert[nt] = e;
                g_tile_row0[nt]   = r;
                g_tile_rows[nt]   = min(BM, offs[e + 1] - r);
                nt++;
            }
        g_ntiles = nt;
        for (int e = 0; e < NEXP; e++) cur[e] = offs[e];
    }
    __syncthreads();
    for (int i = tid; i < B; i += 1024) {
        int e = actions[i] & (NEXP - 1);
        unsigned m = __match_any_sync(0xFFFFFFFFu, e);
        int leader = __ffs(m) - 1;
        int rank = __popc(m & ((1u << lane) - 1u));
        int base = 0;
        if (lane == leader) base = atomicAdd(&cur[e], __popc(m));
        base = __shfl_sync(0xFFFFFFFFu, base, leader);
        g_perm[base + rank] = i;
    }
}

// ---------------------------------------------------------------------------
// Kernel 2: W fp32 -> bf16 hi/lo
// ---------------------------------------------------------------------------
__global__ void convert_w(const float* __restrict__ W) {
    size_t i = ((size_t)blockIdx.x * 256 + threadIdx.x) * 4;
    float4 v = *(const float4*)(W + i);
    __nv_bfloat16 h0 = __float2bfloat16(v.x), h1 = __float2bfloat16(v.y);
    __nv_bfloat16 h2 = __float2bfloat16(v.z), h3 = __float2bfloat16(v.w);
    __nv_bfloat16 l0 = __float2bfloat16(v.x - __bfloat162float(h0));
    __nv_bfloat16 l1 = __float2bfloat16(v.y - __bfloat162float(h1));
    __nv_bfloat16 l2 = __float2bfloat16(v.z - __bfloat162float(h2));
    __nv_bfloat16 l3 = __float2bfloat16(v.w - __bfloat162float(h3));
    *(__nv_bfloat162*)(g_wh + i)     = __nv_bfloat162(h0, h1);
    *(__nv_bfloat162*)(g_wh + i + 2) = __nv_bfloat162(h2, h3);
    *(__nv_bfloat162*)(g_wl + i)     = __nv_bfloat162(l0, l1);
    *(__nv_bfloat162*)(g_wl + i + 2) = __nv_bfloat162(l2, l3);
}

// ---------------------------------------------------------------------------
// Kernel 3: gather x rows by perm + split to bf16 hi/lo (permuted copies)
// ---------------------------------------------------------------------------
__global__ void gather_x(const float* __restrict__ xs) {
    int p = blockIdx.x;
    int src = g_perm[p];
    const float4* s = (const float4*)(xs + (size_t)src * DIN);
    float4 v = s[threadIdx.x];
    size_t o = (size_t)p * DIN + threadIdx.x * 4;
    __nv_bfloat16 h0 = __float2bfloat16(v.x), h1 = __float2bfloat16(v.y);
    __nv_bfloat16 h2 = __float2bfloat16(v.z), h3 = __float2bfloat16(v.w);
    __nv_bfloat16 l0 = __float2bfloat16(v.x - __bfloat162float(h0));
    __nv_bfloat16 l1 = __float2bfloat16(v.y - __bfloat162float(h1));
    __nv_bfloat16 l2 = __float2bfloat16(v.z - __bfloat162float(h2));
    __nv_bfloat16 l3 = __float2bfloat16(v.w - __bfloat162float(h3));
    *(__nv_bfloat162*)(g_xh + o)     = __nv_bfloat162(h0, h1);
    *(__nv_bfloat162*)(g_xh + o + 2) = __nv_bfloat162(h2, h3);
    *(__nv_bfloat162*)(g_xl + o)     = __nv_bfloat162(l0, l1);
    *(__nv_bfloat162*)(g_xl + o + 2) = __nv_bfloat162(l2, l3);
}

// ---------------------------------------------------------------------------
// Kernel 4: bf16x3 GEMM via mma.sync (HMMA), double-buffered cp.async.
//   D[128,128] = Ah*Bh + Al*Bh + Ah*Bl + bias, scattered to original rows.
// 8 warps: wm = wid&3 (32-row block), wn = wid>>2 (64-col block).
// ---------------------------------------------------------------------------
__global__ __launch_bounds__(256, 2) void gemm_mma(
    const float* __restrict__ bias,
    float* __restrict__ out)
{
    int t = blockIdx.x;
    if (t >= g_ntiles) return;
    const int e     = g_tile_expert[t];
    const int row0  = g_tile_row0[t];
    const int nrows = g_tile_rows[t];
    const int n0    = blockIdx.y * BN;

    extern __shared__ __align__(128) uint8_t smem[];
    const uint32_t sb = smem_to_u32(smem);
    int*   rows_s = (int*)(smem + SMEM_ROWS);
    float* bias_s = (float*)(smem + SMEM_BIAS);

    const int tid  = threadIdx.x;
    const int wid  = tid >> 5;
    const int lane = tid & 31;
    const int wm   = wid & 3;
    const int wn   = wid >> 2;

    if (tid < BM) {
        rows_s[tid] = (tid < nrows) ? g_perm[row0 + tid] : -1;
        bias_s[tid] = bias[e * DOUT + n0 + tid];
    }

    // per-thread loader coords: 2 chunks of 16B per sub-tile
    const int cc0 = tid, cc1 = tid + 256;
    const int r0c = cc0 >> 2, c0c = cc0 & 3;
    const int r1c = cc1 >> 2, c1c = cc1 & 3;
    int gra0 = row0 + r0c; if (gra0 >= B) gra0 = B - 1;
    int gra1 = row0 + r1c; if (gra1 >= B) gra1 = B - 1;
    const size_t xo0 = (size_t)gra0 * DIN + c0c * 8;
    const size_t xo1 = (size_t)gra1 * DIN + c1c * 8;
    const size_t wo0 = (size_t)(e * DOUT + n0 + r0c) * DIN + c0c * 8;
    const size_t wo1 = (size_t)(e * DOUT + n0 + r1c) * DIN + c1c * 8;
    const uint32_t d0 = r0c * (PAD * 2) + c0c * 16;
    const uint32_t d1 = r1c * (PAD * 2) + c1c * 16;

#define LOAD_CHUNK(ch, stg) do {                                   \
        int k0_ = (ch) * BK;                                       \
        uint32_t sB_ = sb + (stg) * STAGE_B;                       \
        cpasync16(sB_ + d0,        g_xh + xo0 + k0_);              \
        cpasync16(sB_ + d1,        g_xh + xo1 + k0_);              \
        cpasync16(sB_ + T_AL + d0, g_xl + xo0 + k0_);              \
        cpasync16(sB_ + T_AL + d1, g_xl + xo1 + k0_);              \
        cpasync16(sB_ + T_BH + d0, g_wh + wo0 + k0_);              \
        cpasync16(sB_ + T_BH + d1, g_wh + wo1 + k0_);              \
        cpasync16(sB_ + T_BL + d0, g_wl + wo0 + k0_);              \
        cpasync16(sB_ + T_BL + d1, g_wl + wo1 + k0_);              \
        CP_COMMIT();                                               \
    } while (0)

    float acc[2][8][4];
#pragma unroll
    for (int i = 0; i < 2; i++)
#pragma unroll
        for (int j = 0; j < 8; j++)
#pragma unroll
            for (int k = 0; k < 4; k++) acc[i][j][k] = 0.0f;

    // precomputed ldmatrix lane offsets (within a sub-tile, per kstep add)
    const uint32_t aoff[2] = {
        (uint32_t)((wm * 32 +  0 + (lane & 15)) * (PAD * 2) + ((lane >> 4) * 8) * 2),
        (uint32_t)((wm * 32 + 16 + (lane & 15)) * (PAD * 2) + ((lane >> 4) * 8) * 2)
    };
    uint32_t boff[4];
#pragma unroll
    for (int np = 0; np < 4; np++) {
        int nr = wn * 64 + np * 16 + (lane & 7) + ((lane >> 4) << 3);
        boff[np] = (uint32_t)(nr * (PAD * 2) + (((lane >> 3) & 1) * 8) * 2);
    }

    LOAD_CHUNK(0, 0);
    for (int ch = 0; ch < NCHUNK; ch++) {
        int stg = ch & 1;
        if (ch + 1 < NCHUNK) {
            LOAD_CHUNK(ch + 1, stg ^ 1);
            CP_WAIT(1);
        } else {
            CP_WAIT(0);
        }
        __syncthreads();

        uint32_t s0 = sb + stg * STAGE_B;
#pragma unroll
        for (int ks = 0; ks < 2; ks++) {
            const uint32_t ko = ks * 32;   // 16 elems * 2B
            uint32_t ah[2][4], al[2][4], bb[4][4];
#pragma unroll
            for (int mt = 0; mt < 2; mt++) {
                ldsm4(ah[mt], s0 + aoff[mt] + ko);
                ldsm4(al[mt], s0 + T_AL + aoff[mt] + ko);
            }
#pragma unroll
            for (int np = 0; np < 4; np++)
                ldsm4(bb[np], s0 + T_BH + boff[np] + ko);
#pragma unroll
            for (int mt = 0; mt < 2; mt++)
#pragma unroll
                for (int np = 0; np < 4; np++) {
                    mma16816(acc[mt][np * 2],     ah[mt], bb[np][0], bb[np][1]);
                    mma16816(acc[mt][np * 2 + 1], ah[mt], bb[np][2], bb[np][3]);
                    mma16816(acc[mt][np * 2],     al[mt], bb[np][0], bb[np][1]);
                    mma16816(acc[mt][np * 2 + 1], al[mt], bb[np][2], bb[np][3]);
                }
#pragma unroll
            for (int np = 0; np < 4; np++)
                ldsm4(bb[np], s0 + T_BL + boff[np] + ko);
#pragma unroll
            for (int mt = 0; mt < 2; mt++)
#pragma unroll
                for (int np = 0; np < 4; np++) {
                    mma16816(acc[mt][np * 2],     ah[mt], bb[np][0], bb[np][1]);
                    mma16816(acc[mt][np * 2 + 1], ah[mt], bb[np][2], bb[np][3]);
                }
        }
        __syncthreads();
    }

    // Epilogue: scatter with bias
#pragma unroll
    for (int mt = 0; mt < 2; mt++) {
        int rbase = wm * 32 + mt * 16 + (lane >> 2);
#pragma unroll
        for (int half = 0; half < 2; half++) {
            int gr = rows_s[rbase + half * 8];
            if (gr < 0) continue;
            float* orow = out + (size_t)gr * DOUT + n0;
#pragma unroll
            for (int nt = 0; nt < 8; nt++) {
                int col = wn * 64 + nt * 8 + (lane & 3) * 2;
                float2 v;
                v.x = acc[mt][nt][half * 2 + 0] + bias_s[col];
                v.y = acc[mt][nt][half * 2 + 1] + bias_s[col + 1];
                *(float2*)(orow + col) = v;
            }
        }
    }
#undef LOAD_CHUNK
}

// ---------------------------------------------------------------------------
// Kernel 5: passthrough tail if harness packs (ys, mxs, actions)
// ---------------------------------------------------------------------------
__global__ void tail_kernel(const int* __restrict__ mxs,
                            const int* __restrict__ actions,
                            float* __restrict__ out, int extra)
{
    int i = blockIdx.x * blockDim.x + threadIdx.x;
    if (i >= B) return;
    const size_t base = (size_t)B * DOUT;
    if (extra >= B)     out[base + i]     = (float)mxs[i];
    if (extra >= 2 * B) out[base + B + i] = (float)actions[i];
}

// ---------------------------------------------------------------------------
// Host launch
// ---------------------------------------------------------------------------
extern "C" void kernel_launch(void* const* d_in, const int* in_sizes, int n_in,
                              void* d_out, int out_size)
{
    const float* xs      = (const float*)d_in[0];
    const int*   mxs     = (const int*)d_in[1];
    const int*   actions = (const int*)d_in[2];
    const float* W       = (const float*)d_in[3];
    const float* bias    = (const float*)d_in[4];
    float*       out     = (float*)d_out;

    static bool attr_done = false;
    if (!attr_done) {
        cudaFuncSetAttribute(gemm_mma, cudaFuncAttributeMaxDynamicSharedMemorySize, SMEM_TOTAL);
        attr_done = true;
    }

    convert_w<<<(NEXP * DOUT * DIN) / (256 * 4), 256>>>(W);
    sort_kernel<<<1, 1024>>>(actions);
    gather_x<<<B, 256>>>(xs);

    dim3 grid(MAX_TILES, DOUT / BN);
    gemm_mma<<<grid, 256, SMEM_TOTAL>>>(bias, out);

    int extra = out_size - B * DOUT;
    if (extra > 0) {
        tail_kernel<<<(B + 255) / 256, 256>>>(mxs, actions, out, extra);
    }
}

// round 7
// speedup vs baseline: 3.3517x; 1.2570x over previous
#include <cuda_runtime.h>
#include <cuda_bf16.h>
#include <cstdint>

// ---------------------------------------------------------------------------
// Problem constants
// ---------------------------------------------------------------------------
#define B      4096
#define DIN    1024
#define DOUT   1024
#define NEXP   8
#define BM     128
#define BN     128
#define BK     32              // bf16 elems per k-chunk (64B rows)
#define NCHUNK (DIN / BK)      // 32
#define MAX_TILES 40
#define NSTG   3

#define TILE_B    (BM * 64)            // 8192 bytes per sub-tile (no padding, swizzled)
#define T_AL      TILE_B
#define T_BH      (2 * TILE_B)
#define T_BL      (3 * TILE_B)
#define STAGE_B   (4 * TILE_B)         // 32768
#define SMEM_ROWS (NSTG * STAGE_B)     // 98304
#define SMEM_BIAS (SMEM_ROWS + 512)
#define SMEM_TOTAL (SMEM_ROWS + 1024)  // 99328 -> 2 CTAs/SM

// XOR swizzle: row r (64B stride), 16B-chunk c in 0..3 -> conflict-free for
// cp.async.128 stores and ldmatrix 8-row phases.
#define SWZ(r, c) ((uint32_t)((r) * 64 + ((((c) ^ (((r) >> 1) & 3))) << 4)))

// ---------------------------------------------------------------------------
// Device-global scratch
// ---------------------------------------------------------------------------
__device__ int g_perm[B];
__device__ int g_tile_expert[MAX_TILES];
__device__ int g_tile_row0[MAX_TILES];
__device__ int g_tile_rows[MAX_TILES];
__device__ int g_ntiles;
__device__ __align__(128) __nv_bfloat16 g_xh[B * DIN];
__device__ __align__(128) __nv_bfloat16 g_xl[B * DIN];
__device__ __align__(128) __nv_bfloat16 g_wh[NEXP * DOUT * DIN];
__device__ __align__(128) __nv_bfloat16 g_wl[NEXP * DOUT * DIN];

// ---------------------------------------------------------------------------
// PTX helpers (baseline sm_80+ ISA only)
// ---------------------------------------------------------------------------
__device__ __forceinline__ uint32_t smem_to_u32(const void* p) {
    uint32_t a;
    asm("{ .reg .u64 t; cvta.to.shared.u64 t, %1; cvt.u32.u64 %0, t; }" : "=r"(a) : "l"(p));
    return a;
}
__device__ __forceinline__ void cpasync16(uint32_t dst, const void* src) {
    asm volatile("cp.async.cg.shared.global [%0], [%1], 16;" :: "r"(dst), "l"(src));
}
#define CP_COMMIT() asm volatile("cp.async.commit_group;" ::: "memory")
#define CP_WAIT(n)  asm volatile("cp.async.wait_group %0;" :: "n"(n) : "memory")

__device__ __forceinline__ void ldsm4(uint32_t* r, uint32_t addr) {
    asm volatile("ldmatrix.sync.aligned.m8n8.x4.shared.b16 {%0,%1,%2,%3}, [%4];"
        : "=r"(r[0]), "=r"(r[1]), "=r"(r[2]), "=r"(r[3]) : "r"(addr));
}
__device__ __forceinline__ void mma16816(float* c, const uint32_t* a, uint32_t b0, uint32_t b1) {
    asm volatile(
        "mma.sync.aligned.m16n8k16.row.col.f32.bf16.bf16.f32 "
        "{%0,%1,%2,%3}, {%4,%5,%6,%7}, {%8,%9}, {%0,%1,%2,%3};"
        : "+f"(c[0]), "+f"(c[1]), "+f"(c[2]), "+f"(c[3])
        : "r"(a[0]), "r"(a[1]), "r"(a[2]), "r"(a[3]), "r"(b0), "r"(b1));
}

// ---------------------------------------------------------------------------
// Kernel 1: warp-aggregated counting sort
// ---------------------------------------------------------------------------
__global__ void sort_kernel(const int* __restrict__ actions) {
    __shared__ int cnt[NEXP];
    __shared__ int offs[NEXP + 1];
    __shared__ int cur[NEXP];
    int tid = threadIdx.x;
    int lane = tid & 31;
    if (tid < NEXP) cnt[tid] = 0;
    __syncthreads();
    for (int i = tid; i < B; i += 1024) {
        int e = actions[i] & (NEXP - 1);
        unsigned m = __match_any_sync(0xFFFFFFFFu, e);
        if (lane == (__ffs(m) - 1)) atomicAdd(&cnt[e], __popc(m));
    }
    __syncthreads();
    if (tid == 0) {
        int s = 0;
        for (int e = 0; e < NEXP; e++) { offs[e] = s; s += cnt[e]; }
        offs[NEXP] = s;
        int nt = 0;
        for (int e = 0; e < NEXP; e++)
            for (int r = offs[e]; r < offs[e + 1]; r += BM) {
                g_tile_expert[nt] = e;
                g_tile_row0[nt]   = r;
                g_tile_rows[nt]   = min(BM, offs[e + 1] - r);
                nt++;
            }
        g_ntiles = nt;
        for (int e = 0; e < NEXP; e++) cur[e] = offs[e];
    }
    __syncthreads();
    for (int i = tid; i < B; i += 1024) {
        int e = actions[i] & (NEXP - 1);
        unsigned m = __match_any_sync(0xFFFFFFFFu, e);
        int leader = __ffs(m) - 1;
        int rank = __popc(m & ((1u << lane) - 1u));
        int base = 0;
        if (lane == leader) base = atomicAdd(&cur[e], __popc(m));
        base = __shfl_sync(0xFFFFFFFFu, base, leader);
        g_perm[base + rank] = i;
    }
}

// ---------------------------------------------------------------------------
// Kernel 2 (fused): blocks [0,8192) convert W; blocks [8192,12288) gather x
// ---------------------------------------------------------------------------
#define NWBLK 8192
__global__ void prep_kernel(const float* __restrict__ W, const float* __restrict__ xs) {
    if (blockIdx.x < NWBLK) {
        size_t i = ((size_t)blockIdx.x * 256 + threadIdx.x) * 4;
        float4 v = *(const float4*)(W + i);
        __nv_bfloat16 h0 = __float2bfloat16(v.x), h1 = __float2bfloat16(v.y);
        __nv_bfloat16 h2 = __float2bfloat16(v.z), h3 = __float2bfloat16(v.w);
        __nv_bfloat16 l0 = __float2bfloat16(v.x - __bfloat162float(h0));
        __nv_bfloat16 l1 = __float2bfloat16(v.y - __bfloat162float(h1));
        __nv_bfloat16 l2 = __float2bfloat16(v.z - __bfloat162float(h2));
        __nv_bfloat16 l3 = __float2bfloat16(v.w - __bfloat162float(h3));
        *(__nv_bfloat162*)(g_wh + i)     = __nv_bfloat162(h0, h1);
        *(__nv_bfloat162*)(g_wh + i + 2) = __nv_bfloat162(h2, h3);
        *(__nv_bfloat162*)(g_wl + i)     = __nv_bfloat162(l0, l1);
        *(__nv_bfloat162*)(g_wl + i + 2) = __nv_bfloat162(l2, l3);
    } else {
        int p = blockIdx.x - NWBLK;
        int src = g_perm[p];
        const float4* s = (const float4*)(xs + (size_t)src * DIN);
        float4 v = s[threadIdx.x];
        size_t o = (size_t)p * DIN + threadIdx.x * 4;
        __nv_bfloat16 h0 = __float2bfloat16(v.x), h1 = __float2bfloat16(v.y);
        __nv_bfloat16 h2 = __float2bfloat16(v.z), h3 = __float2bfloat16(v.w);
        __nv_bfloat16 l0 = __float2bfloat16(v.x - __bfloat162float(h0));
        __nv_bfloat16 l1 = __float2bfloat16(v.y - __bfloat162float(h1));
        __nv_bfloat16 l2 = __float2bfloat16(v.z - __bfloat162float(h2));
        __nv_bfloat16 l3 = __float2bfloat16(v.w - __bfloat162float(h3));
        *(__nv_bfloat162*)(g_xh + o)     = __nv_bfloat162(h0, h1);
        *(__nv_bfloat162*)(g_xh + o + 2) = __nv_bfloat162(h2, h3);
        *(__nv_bfloat162*)(g_xl + o)     = __nv_bfloat162(l0, l1);
        *(__nv_bfloat162*)(g_xl + o + 2) = __nv_bfloat162(l2, l3);
    }
}

// ---------------------------------------------------------------------------
// Kernel 3: bf16x3 GEMM via mma.sync, 3-stage cp.async, swizzled smem.
// 8 warps: wm = wid&3 (32-row block), wn = wid>>2 (64-col block).
// ---------------------------------------------------------------------------
__global__ __launch_bounds__(256, 2) void gemm_mma(
    const float* __restrict__ bias,
    float* __restrict__ out)
{
    int t = blockIdx.x;
    if (t >= g_ntiles) return;
    const int e     = g_tile_expert[t];
    const int row0  = g_tile_row0[t];
    const int nrows = g_tile_rows[t];
    const int n0    = blockIdx.y * BN;

    extern __shared__ __align__(128) uint8_t smem[];
    const uint32_t sb = smem_to_u32(smem);
    int*   rows_s = (int*)(smem + SMEM_ROWS);
    float* bias_s = (float*)(smem + SMEM_BIAS);

    const int tid  = threadIdx.x;
    const int wid  = tid >> 5;
    const int lane = tid & 31;
    const int wm   = wid & 3;
    const int wn   = wid >> 2;

    if (tid < BM) {
        rows_s[tid] = (tid < nrows) ? g_perm[row0 + tid] : -1;
        bias_s[tid] = bias[e * DOUT + n0 + tid];
    }

    // per-thread loader coords: 2 chunks of 16B per sub-tile
    const int cc0 = tid, cc1 = tid + 256;
    const int r0c = cc0 >> 2, c0c = cc0 & 3;
    const int r1c = cc1 >> 2, c1c = cc1 & 3;
    int gra0 = row0 + r0c; if (gra0 >= B) gra0 = B - 1;
    int gra1 = row0 + r1c; if (gra1 >= B) gra1 = B - 1;
    const size_t xo0 = (size_t)gra0 * DIN + c0c * 8;
    const size_t xo1 = (size_t)gra1 * DIN + c1c * 8;
    const size_t wo0 = (size_t)(e * DOUT + n0 + r0c) * DIN + c0c * 8;
    const size_t wo1 = (size_t)(e * DOUT + n0 + r1c) * DIN + c1c * 8;
    const uint32_t d0 = SWZ(r0c, c0c);
    const uint32_t d1 = SWZ(r1c, c1c);

#define LOAD_CHUNK(ch, stg) do {                                   \
        int k0_ = (ch) * BK;                                       \
        uint32_t sB_ = sb + (stg) * STAGE_B;                       \
        cpasync16(sB_ + d0,        g_xh + xo0 + k0_);              \
        cpasync16(sB_ + d1,        g_xh + xo1 + k0_);              \
        cpasync16(sB_ + T_AL + d0, g_xl + xo0 + k0_);              \
        cpasync16(sB_ + T_AL + d1, g_xl + xo1 + k0_);              \
        cpasync16(sB_ + T_BH + d0, g_wh + wo0 + k0_);              \
        cpasync16(sB_ + T_BH + d1, g_wh + wo1 + k0_);              \
        cpasync16(sB_ + T_BL + d0, g_wl + wo0 + k0_);              \
        cpasync16(sB_ + T_BL + d1, g_wl + wo1 + k0_);              \
        CP_COMMIT();                                               \
    } while (0)

    float acc[2][8][4];
#pragma unroll
    for (int i = 0; i < 2; i++)
#pragma unroll
        for (int j = 0; j < 8; j++)
#pragma unroll
            for (int k = 0; k < 4; k++) acc[i][j][k] = 0.0f;

    // ldmatrix lane offsets, precomputed for both k-steps (swizzled)
    uint32_t aoff[2][2], boff[4][2];
#pragma unroll
    for (int mt = 0; mt < 2; mt++) {
        int r = wm * 32 + mt * 16 + (lane & 15);
#pragma unroll
        for (int ks = 0; ks < 2; ks++)
            aoff[mt][ks] = SWZ(r, ks * 2 + (lane >> 4));
    }
#pragma unroll
    for (int np = 0; np < 4; np++) {
        int nr = wn * 64 + np * 16 + (lane & 7) + ((lane >> 4) << 3);
#pragma unroll
        for (int ks = 0; ks < 2; ks++)
            boff[np][ks] = SWZ(nr, ks * 2 + ((lane >> 3) & 1));
    }

    LOAD_CHUNK(0, 0);
    LOAD_CHUNK(1, 1);
    for (int ch = 0; ch < NCHUNK; ch++) {
        int stg = ch % NSTG;
        if (ch < NCHUNK - 1) { CP_WAIT(1); } else { CP_WAIT(0); }
        __syncthreads();

        uint32_t s0 = sb + stg * STAGE_B;
#pragma unroll
        for (int ks = 0; ks < 2; ks++) {
            uint32_t ah[2][4], al[2][4], bb[4][4];
#pragma unroll
            for (int mt = 0; mt < 2; mt++) {
                ldsm4(ah[mt], s0 + aoff[mt][ks]);
                ldsm4(al[mt], s0 + T_AL + aoff[mt][ks]);
            }
#pragma unroll
            for (int np = 0; np < 4; np++)
                ldsm4(bb[np], s0 + T_BH + boff[np][ks]);
#pragma unroll
            for (int mt = 0; mt < 2; mt++)
#pragma unroll
                for (int np = 0; np < 4; np++) {
                    mma16816(acc[mt][np * 2],     ah[mt], bb[np][0], bb[np][1]);
                    mma16816(acc[mt][np * 2 + 1], ah[mt], bb[np][2], bb[np][3]);
                    mma16816(acc[mt][np * 2],     al[mt], bb[np][0], bb[np][1]);
                    mma16816(acc[mt][np * 2 + 1], al[mt], bb[np][2], bb[np][3]);
                }
#pragma unroll
            for (int np = 0; np < 4; np++)
                ldsm4(bb[np], s0 + T_BL + boff[np][ks]);
#pragma unroll
            for (int mt = 0; mt < 2; mt++)
#pragma unroll
                for (int np = 0; np < 4; np++) {
                    mma16816(acc[mt][np * 2],     ah[mt], bb[np][0], bb[np][1]);
                    mma16816(acc[mt][np * 2 + 1], ah[mt], bb[np][2], bb[np][3]);
                }
        }
        // prefetch chunk ch+2 into slot (ch+2)%3 (buffer consumed in iter ch-1;
        // all warps passed this iter's barrier => safe)
        if (ch + 2 < NCHUNK) LOAD_CHUNK(ch + 2, (ch + 2) % NSTG);
    }

    // Epilogue: scatter with bias
#pragma unroll
    for (int mt = 0; mt < 2; mt++) {
        int rbase = wm * 32 + mt * 16 + (lane >> 2);
#pragma unroll
        for (int half = 0; half < 2; half++) {
            int gr = rows_s[rbase + half * 8];
            if (gr < 0) continue;
            float* orow = out + (size_t)gr * DOUT + n0;
#pragma unroll
            for (int nt = 0; nt < 8; nt++) {
                int col = wn * 64 + nt * 8 + (lane & 3) * 2;
                float2 v;
                v.x = acc[mt][nt][half * 2 + 0] + bias_s[col];
                v.y = acc[mt][nt][half * 2 + 1] + bias_s[col + 1];
                *(float2*)(orow + col) = v;
            }
        }
    }
#undef LOAD_CHUNK
}

// ---------------------------------------------------------------------------
// Kernel 4: passthrough tail if harness packs (ys, mxs, actions)
// ---------------------------------------------------------------------------
__global__ void tail_kernel(const int* __restrict__ mxs,
                            const int* __restrict__ actions,
                            float* __restrict__ out, int extra)
{
    int i = blockIdx.x * blockDim.x + threadIdx.x;
    if (i >= B) return;
    const size_t base = (size_t)B * DOUT;
    if (extra >= B)     out[base + i]     = (float)mxs[i];
    if (extra >= 2 * B) out[base + B + i] = (float)actions[i];
}

// ---------------------------------------------------------------------------
// Host launch
// ---------------------------------------------------------------------------
extern "C" void kernel_launch(void* const* d_in, const int* in_sizes, int n_in,
                              void* d_out, int out_size)
{
    const float* xs      = (const float*)d_in[0];
    const int*   mxs     = (const int*)d_in[1];
    const int*   actions = (const int*)d_in[2];
    const float* W       = (const float*)d_in[3];
    const float* bias    = (const float*)d_in[4];
    float*       out     = (float*)d_out;

    static bool attr_done = false;
    if (!attr_done) {
        cudaFuncSetAttribute(gemm_mma, cudaFuncAttributeMaxDynamicSharedMemorySize, SMEM_TOTAL);
        attr_done = true;
    }

    sort_kernel<<<1, 1024>>>(actions);
    prep_kernel<<<NWBLK + B, 256>>>(W, xs);

    dim3 grid(MAX_TILES, DOUT / BN);
    gemm_mma<<<grid, 256, SMEM_TOTAL>>>(bias, out);

    int extra = out_size - B * DOUT;
    if (extra > 0) {
        tail_kernel<<<(B + 255) / 256, 256>>>(mxs, actions, out, extra);
    }
}

// round 8
// speedup vs baseline: 3.4261x; 1.0222x over previous
#include <cuda_runtime.h>
#include <cuda_bf16.h>
#include <cstdint>

// ---------------------------------------------------------------------------
// Problem constants
// ---------------------------------------------------------------------------
#define B      4096
#define DIN    1024
#define DOUT   1024
#define NEXP   8
#define BM     128
#define BN     128
#define BK     32              // bf16 elems per k-chunk (64B rows)
#define NCHUNK (DIN / BK)      // 32
#define MAX_TILES 40
#define NSTG   3

#define TILE_B    (BM * 64)            // 8192 bytes per sub-tile (swizzled, no pad)
#define T_AL      TILE_B
#define T_BH      (2 * TILE_B)
#define T_BL      (3 * TILE_B)
#define STAGE_B   (4 * TILE_B)         // 32768
#define SMEM_ROWS (NSTG * STAGE_B)     // 98304
#define SMEM_BIAS (SMEM_ROWS + 512)
#define SMEM_TOTAL (SMEM_ROWS + 1024)  // 99328 -> 2 CTAs/SM

// XOR swizzle: row r (64B stride), 16B-chunk c in 0..3
#define SWZ(r, c) ((uint32_t)((r) * 64 + ((((c) ^ (((r) >> 1) & 3))) << 4)))

// ---------------------------------------------------------------------------
// Device-global scratch
// ---------------------------------------------------------------------------
__device__ int g_perm[B];
__device__ int g_tile_expert[MAX_TILES];
__device__ int g_tile_row0[MAX_TILES];
__device__ int g_tile_rows[MAX_TILES];
__device__ int g_ntiles;
__device__ __align__(128) __nv_bfloat16 g_xh[B * DIN];
__device__ __align__(128) __nv_bfloat16 g_xl[B * DIN];
__device__ __align__(128) __nv_bfloat16 g_wh[NEXP * DOUT * DIN];
__device__ __align__(128) __nv_bfloat16 g_wl[NEXP * DOUT * DIN];

// ---------------------------------------------------------------------------
// PTX helpers (baseline sm_80+ ISA only)
// ---------------------------------------------------------------------------
__device__ __forceinline__ uint32_t smem_to_u32(const void* p) {
    uint32_t a;
    asm("{ .reg .u64 t; cvta.to.shared.u64 t, %1; cvt.u32.u64 %0, t; }" : "=r"(a) : "l"(p));
    return a;
}
__device__ __forceinline__ void cpasync16(uint32_t dst, const void* src) {
    asm volatile("cp.async.cg.shared.global [%0], [%1], 16;" :: "r"(dst), "l"(src));
}
#define CP_COMMIT() asm volatile("cp.async.commit_group;" ::: "memory")
#define CP_WAIT(n)  asm volatile("cp.async.wait_group %0;" :: "n"(n) : "memory")

__device__ __forceinline__ void ldsm4(uint32_t* r, uint32_t addr) {
    asm volatile("ldmatrix.sync.aligned.m8n8.x4.shared.b16 {%0,%1,%2,%3}, [%4];"
        : "=r"(r[0]), "=r"(r[1]), "=r"(r[2]), "=r"(r[3]) : "r"(addr));
}
__device__ __forceinline__ void mma16816(float* c, const uint32_t* a, uint32_t b0, uint32_t b1) {
    asm volatile(
        "mma.sync.aligned.m16n8k16.row.col.f32.bf16.bf16.f32 "
        "{%0,%1,%2,%3}, {%4,%5,%6,%7}, {%8,%9}, {%0,%1,%2,%3};"
        : "+f"(c[0]), "+f"(c[1]), "+f"(c[2]), "+f"(c[3])
        : "r"(a[0]), "r"(a[1]), "r"(a[2]), "r"(a[3]), "r"(b0), "r"(b1));
}

// ---------------------------------------------------------------------------
// Kernel 1: counting sort, single pass over actions held in registers
// ---------------------------------------------------------------------------
__global__ void sort_kernel(const int* __restrict__ actions) {
    __shared__ int cnt[NEXP];
    __shared__ int offs[NEXP + 1];
    __shared__ int cur[NEXP];
    int tid = threadIdx.x;
    int lane = tid & 31;
    if (tid < NEXP) cnt[tid] = 0;
    __syncthreads();
    int4 av = ((const int4*)actions)[tid];           // 4 elems per thread, one load
    int ev[4] = { av.x & 7, av.y & 7, av.z & 7, av.w & 7 };
#pragma unroll
    for (int j = 0; j < 4; j++) {
        unsigned m = __match_any_sync(0xFFFFFFFFu, ev[j]);
        if (lane == (__ffs(m) - 1)) atomicAdd(&cnt[ev[j]], __popc(m));
    }
    __syncthreads();
    if (tid == 0) {
        int s = 0;
        for (int e = 0; e < NEXP; e++) { offs[e] = s; s += cnt[e]; }
        offs[NEXP] = s;
        int nt = 0;
        for (int e = 0; e < NEXP; e++)
            for (int r = offs[e]; r < offs[e + 1]; r += BM) {
                g_tile_expert[nt] = e;
                g_tile_row0[nt]   = r;
                g_tile_rows[nt]   = min(BM, offs[e + 1] - r);
                nt++;
            }
        g_ntiles = nt;
        for (int e = 0; e < NEXP; e++) cur[e] = offs[e];
    }
    __syncthreads();
#pragma unroll
    for (int j = 0; j < 4; j++) {
        int i = tid * 4 + j;
        int e = ev[j];
        unsigned m = __match_any_sync(0xFFFFFFFFu, e);
        int leader = __ffs(m) - 1;
        int rank = __popc(m & ((1u << lane) - 1u));
        int base = 0;
        if (lane == leader) base = atomicAdd(&cur[e], __popc(m));
        base = __shfl_sync(0xFFFFFFFFu, base, leader);
        g_perm[base + rank] = i;
    }
}

// ---------------------------------------------------------------------------
// Kernel 2 (fused): [0,NWBLK) convert W; [NWBLK,NWBLK+B) gather x;
//                   [NWBLK+B, NWBLK+B+16) passthrough tail.
// ---------------------------------------------------------------------------
#define NWBLK 8192
__global__ void prep_kernel(const float* __restrict__ W, const float* __restrict__ xs,
                            const int* __restrict__ mxs, const int* __restrict__ actions,
                            float* __restrict__ out, int extra) {
    if (blockIdx.x < NWBLK) {
        size_t i = ((size_t)blockIdx.x * 256 + threadIdx.x) * 4;
        float4 v = *(const float4*)(W + i);
        __nv_bfloat16 h0 = __float2bfloat16(v.x), h1 = __float2bfloat16(v.y);
        __nv_bfloat16 h2 = __float2bfloat16(v.z), h3 = __float2bfloat16(v.w);
        __nv_bfloat16 l0 = __float2bfloat16(v.x - __bfloat162float(h0));
        __nv_bfloat16 l1 = __float2bfloat16(v.y - __bfloat162float(h1));
        __nv_bfloat16 l2 = __float2bfloat16(v.z - __bfloat162float(h2));
        __nv_bfloat16 l3 = __float2bfloat16(v.w - __bfloat162float(h3));
        *(__nv_bfloat162*)(g_wh + i)     = __nv_bfloat162(h0, h1);
        *(__nv_bfloat162*)(g_wh + i + 2) = __nv_bfloat162(h2, h3);
        *(__nv_bfloat162*)(g_wl + i)     = __nv_bfloat162(l0, l1);
        *(__nv_bfloat162*)(g_wl + i + 2) = __nv_bfloat162(l2, l3);
    } else if (blockIdx.x < NWBLK + B) {
        int p = blockIdx.x - NWBLK;
        int src = g_perm[p];
        const float4* s = (const float4*)(xs + (size_t)src * DIN);
        float4 v = s[threadIdx.x];
        size_t o = (size_t)p * DIN + threadIdx.x * 4;
        __nv_bfloat16 h0 = __float2bfloat16(v.x), h1 = __float2bfloat16(v.y);
        __nv_bfloat16 h2 = __float2bfloat16(v.z), h3 = __float2bfloat16(v.w);
        __nv_bfloat16 l0 = __float2bfloat16(v.x - __bfloat162float(h0));
        __nv_bfloat16 l1 = __float2bfloat16(v.y - __bfloat162float(h1));
        __nv_bfloat16 l2 = __float2bfloat16(v.z - __bfloat162float(h2));
        __nv_bfloat16 l3 = __float2bfloat16(v.w - __bfloat162float(h3));
        *(__nv_bfloat162*)(g_xh + o)     = __nv_bfloat162(h0, h1);
        *(__nv_bfloat162*)(g_xh + o + 2) = __nv_bfloat162(h2, h3);
        *(__nv_bfloat162*)(g_xl + o)     = __nv_bfloat162(l0, l1);
        *(__nv_bfloat162*)(g_xl + o + 2) = __nv_bfloat162(l2, l3);
    } else {
        int i = (blockIdx.x - NWBLK - B) * 256 + threadIdx.x;
        if (i < B && extra > 0) {
            const size_t base = (size_t)B * DOUT;
            if (extra >= B)     out[base + i]     = (float)mxs[i];
            if (extra >= 2 * B) out[base + B + i] = (float)actions[i];
        }
    }
}

// ---------------------------------------------------------------------------
// Kernel 3: bf16x3 GEMM via mma.sync, 3-stage cp.async, swizzled smem.
// 8 warps: wm = wid&3 (32-row block), wn = wid>>2 (64-col block).
// ---------------------------------------------------------------------------
__global__ __launch_bounds__(256, 2) void gemm_mma(
    const float* __restrict__ bias,
    float* __restrict__ out)
{
    int t = blockIdx.x;
    if (t >= g_ntiles) return;
    const int e     = g_tile_expert[t];
    const int row0  = g_tile_row0[t];
    const int nrows = g_tile_rows[t];
    const int n0    = blockIdx.y * BN;

    extern __shared__ __align__(128) uint8_t smem[];
    const uint32_t sb = smem_to_u32(smem);
    int*   rows_s = (int*)(smem + SMEM_ROWS);
    float* bias_s = (float*)(smem + SMEM_BIAS);

    const int tid  = threadIdx.x;
    const int wid  = tid >> 5;
    const int lane = tid & 31;
    const int wm   = wid & 3;
    const int wn   = wid >> 2;

    if (tid < BM) {
        rows_s[tid] = (tid < nrows) ? g_perm[row0 + tid] : -1;
        bias_s[tid] = bias[e * DOUT + n0 + tid];
    }

    // per-thread loader coords: 2 chunks of 16B per sub-tile
    const int cc0 = tid, cc1 = tid + 256;
    const int r0c = cc0 >> 2, c0c = cc0 & 3;
    const int r1c = cc1 >> 2, c1c = cc1 & 3;
    int gra0 = row0 + r0c; if (gra0 >= B) gra0 = B - 1;
    int gra1 = row0 + r1c; if (gra1 >= B) gra1 = B - 1;
    const size_t xo0 = (size_t)gra0 * DIN + c0c * 8;
    const size_t xo1 = (size_t)gra1 * DIN + c1c * 8;
    const size_t wo0 = (size_t)(e * DOUT + n0 + r0c) * DIN + c0c * 8;
    const size_t wo1 = (size_t)(e * DOUT + n0 + r1c) * DIN + c1c * 8;
    const uint32_t d0 = SWZ(r0c, c0c);
    const uint32_t d1 = SWZ(r1c, c1c);

#define LOAD_CHUNK(ch, stg) do {                                   \
        int k0_ = (ch) * BK;                                       \
        uint32_t sB_ = sb + (stg) * STAGE_B;                       \
        cpasync16(sB_ + d0,        g_xh + xo0 + k0_);              \
        cpasync16(sB_ + d1,        g_xh + xo1 + k0_);              \
        cpasync16(sB_ + T_AL + d0, g_xl + xo0 + k0_);              \
        cpasync16(sB_ + T_AL + d1, g_xl + xo1 + k0_);              \
        cpasync16(sB_ + T_BH + d0, g_wh + wo0 + k0_);              \
        cpasync16(sB_ + T_BH + d1, g_wh + wo1 + k0_);              \
        cpasync16(sB_ + T_BL + d0, g_wl + wo0 + k0_);              \
        cpasync16(sB_ + T_BL + d1, g_wl + wo1 + k0_);              \
        CP_COMMIT();                                               \
    } while (0)

    float acc[2][8][4];
#pragma unroll
    for (int i = 0; i < 2; i++)
#pragma unroll
        for (int j = 0; j < 8; j++)
#pragma unroll
            for (int k = 0; k < 4; k++) acc[i][j][k] = 0.0f;

    // ldmatrix lane offsets, precomputed for both k-steps (swizzled)
    uint32_t aoff[2][2], boff[4][2];
#pragma unroll
    for (int mt = 0; mt < 2; mt++) {
        int r = wm * 32 + mt * 16 + (lane & 15);
#pragma unroll
        for (int ks = 0; ks < 2; ks++)
            aoff[mt][ks] = SWZ(r, ks * 2 + (lane >> 4));
    }
#pragma unroll
    for (int np = 0; np < 4; np++) {
        int nr = wn * 64 + np * 16 + (lane & 7) + ((lane >> 4) << 3);
#pragma unroll
        for (int ks = 0; ks < 2; ks++)
            boff[np][ks] = SWZ(nr, ks * 2 + ((lane >> 3) & 1));
    }

    LOAD_CHUNK(0, 0);
    LOAD_CHUNK(1, 1);
    for (int ch = 0; ch < NCHUNK; ch++) {
        int stg = ch % NSTG;
        if (ch < NCHUNK - 1) { CP_WAIT(1); } else { CP_WAIT(0); }
        __syncthreads();

        uint32_t s0 = sb + stg * STAGE_B;
#pragma unroll
        for (int ks = 0; ks < 2; ks++) {
            uint32_t ah[2][4], al[2][4], bb[4][4];
            // phase 1: ah + bh loads, then AhBh mmas (hide bh latency)
#pragma unroll
            for (int mt = 0; mt < 2; mt++)
                ldsm4(ah[mt], s0 + aoff[mt][ks]);
#pragma unroll
            for (int np = 0; np < 4; np++)
                ldsm4(bb[np], s0 + T_BH + boff[np][ks]);
#pragma unroll
            for (int mt = 0; mt < 2; mt++)
#pragma unroll
                for (int np = 0; np < 4; np++) {
                    mma16816(acc[mt][np * 2],     ah[mt], bb[np][0], bb[np][1]);
                    mma16816(acc[mt][np * 2 + 1], ah[mt], bb[np][2], bb[np][3]);
                }
            // phase 2: al loads under AhBh issue, then AlBh mmas
#pragma unroll
            for (int mt = 0; mt < 2; mt++)
                ldsm4(al[mt], s0 + T_AL + aoff[mt][ks]);
#pragma unroll
            for (int mt = 0; mt < 2; mt++)
#pragma unroll
                for (int np = 0; np < 4; np++) {
                    mma16816(acc[mt][np * 2],     al[mt], bb[np][0], bb[np][1]);
                    mma16816(acc[mt][np * 2 + 1], al[mt], bb[np][2], bb[np][3]);
                }
            // phase 3: bl loads under AlBh issue, then AhBl mmas
#pragma unroll
            for (int np = 0; np < 4; np++)
                ldsm4(bb[np], s0 + T_BL + boff[np][ks]);
#pragma unroll
            for (int mt = 0; mt < 2; mt++)
#pragma unroll
                for (int np = 0; np < 4; np++) {
                    mma16816(acc[mt][np * 2],     ah[mt], bb[np][0], bb[np][1]);
                    mma16816(acc[mt][np * 2 + 1], ah[mt], bb[np][2], bb[np][3]);
                }
        }
        // prefetch chunk ch+2 into slot (ch+2)%3
        if (ch + 2 < NCHUNK) LOAD_CHUNK(ch + 2, (ch + 2) % NSTG);
    }

    // Epilogue: scatter with bias
#pragma unroll
    for (int mt = 0; mt < 2; mt++) {
        int rbase = wm * 32 + mt * 16 + (lane >> 2);
#pragma unroll
        for (int half = 0; half < 2; half++) {
            int gr = rows_s[rbase + half * 8];
            if (gr < 0) continue;
            float* orow = out + (size_t)gr * DOUT + n0;
#pragma unroll
            for (int nt = 0; nt < 8; nt++) {
                int col = wn * 64 + nt * 8 + (lane & 3) * 2;
                float2 v;
                v.x = acc[mt][nt][half * 2 + 0] + bias_s[col];
                v.y = acc[mt][nt][half * 2 + 1] + bias_s[col + 1];
                *(float2*)(orow + col) = v;
            }
        }
    }
#undef LOAD_CHUNK
}

// ---------------------------------------------------------------------------
// Host launch
// ---------------------------------------------------------------------------
extern "C" void kernel_launch(void* const* d_in, const int* in_sizes, int n_in,
                              void* d_out, int out_size)
{
    const float* xs      = (const float*)d_in[0];
    const int*   mxs     = (const int*)d_in[1];
    const int*   actions = (const int*)d_in[2];
    const float* W       = (const float*)d_in[3];
    const float* bias    = (const float*)d_in[4];
    float*       out     = (float*)d_out;

    static bool attr_done = false;
    if (!attr_done) {
        cudaFuncSetAttribute(gemm_mma, cudaFuncAttributeMaxDynamicSharedMemorySize, SMEM_TOTAL);
        attr_done = true;
    }

    int extra = out_size - B * DOUT;

    sort_kernel<<<1, 1024>>>(actions);
    prep_kernel<<<NWBLK + B + 16, 256>>>(W, xs, mxs, actions, out, extra);

    dim3 grid(MAX_TILES, DOUT / BN);
    gemm_mma<<<grid, 256, SMEM_TOTAL>>>(bias, out);
}

// round 9
// speedup vs baseline: 3.5292x; 1.0301x over previous
#include <cuda_runtime.h>
#include <cuda_bf16.h>
#include <cstdint>

// ---------------------------------------------------------------------------
// Problem constants
// ---------------------------------------------------------------------------
#define B      4096
#define DIN    1024
#define DOUT   1024
#define NEXP   8
#define BM     128
#define BN     128
#define BK     32              // bf16 elems per k-chunk (64B rows)
#define NCHUNK (DIN / BK)      // 32
#define MAX_TILES 40
#define NSTG   3

#define TILE_B    (BM * 64)            // 8192 bytes per sub-tile (swizzled, no pad)
#define T_AL      TILE_B
#define T_BH      (2 * TILE_B)
#define T_BL      (3 * TILE_B)
#define STAGE_B   (4 * TILE_B)         // 32768
#define SMEM_ROWS (NSTG * STAGE_B)     // 98304
#define SMEM_BIAS (SMEM_ROWS + 512)
#define SMEM_TOTAL (SMEM_ROWS + 1024)  // 99328 -> 2 CTAs/SM

// XOR swizzle: row r (64B stride), 16B-chunk c in 0..3
#define SWZ(r, c) ((uint32_t)((r) * 64 + ((((c) ^ (((r) >> 1) & 3))) << 4)))

// ---------------------------------------------------------------------------
// Device-global scratch
// ---------------------------------------------------------------------------
__device__ int g_perm[B];
__device__ int g_tile_expert[MAX_TILES];
__device__ int g_tile_row0[MAX_TILES];
__device__ int g_tile_rows[MAX_TILES];
__device__ int g_ntiles;
__device__ __align__(128) __nv_bfloat16 g_xh[B * DIN];            // ORIGINAL row order
__device__ __align__(128) __nv_bfloat16 g_xl[B * DIN];
__device__ __align__(128) __nv_bfloat16 g_wh[NEXP * DOUT * DIN];
__device__ __align__(128) __nv_bfloat16 g_wl[NEXP * DOUT * DIN];

// ---------------------------------------------------------------------------
// PTX helpers (baseline sm_80+ ISA only)
// ---------------------------------------------------------------------------
__device__ __forceinline__ uint32_t smem_to_u32(const void* p) {
    uint32_t a;
    asm("{ .reg .u64 t; cvta.to.shared.u64 t, %1; cvt.u32.u64 %0, t; }" : "=r"(a) : "l"(p));
    return a;
}
__device__ __forceinline__ void cpasync16(uint32_t dst, const void* src) {
    asm volatile("cp.async.cg.shared.global [%0], [%1], 16;" :: "r"(dst), "l"(src));
}
#define CP_COMMIT() asm volatile("cp.async.commit_group;" ::: "memory")
#define CP_WAIT(n)  asm volatile("cp.async.wait_group %0;" :: "n"(n) : "memory")

__device__ __forceinline__ void ldsm4(uint32_t* r, uint32_t addr) {
    asm volatile("ldmatrix.sync.aligned.m8n8.x4.shared.b16 {%0,%1,%2,%3}, [%4];"
        : "=r"(r[0]), "=r"(r[1]), "=r"(r[2]), "=r"(r[3]) : "r"(addr));
}
__device__ __forceinline__ void mma16816(float* c, const uint32_t* a, uint32_t b0, uint32_t b1) {
    asm volatile(
        "mma.sync.aligned.m16n8k16.row.col.f32.bf16.bf16.f32 "
        "{%0,%1,%2,%3}, {%4,%5,%6,%7}, {%8,%9}, {%0,%1,%2,%3};"
        : "+f"(c[0]), "+f"(c[1]), "+f"(c[2]), "+f"(c[3])
        : "r"(a[0]), "r"(a[1]), "r"(a[2]), "r"(a[3]), "r"(b0), "r"(b1));
}

// ---------------------------------------------------------------------------
// Sort body (runs as block 0 of prep grid, blockDim 256 -> 16 elems/thread)
// ---------------------------------------------------------------------------
__device__ void sort_body(const int* __restrict__ actions) {
    __shared__ int cnt[NEXP];
    __shared__ int offs[NEXP + 1];
    __shared__ int cur[NEXP];
    int tid = threadIdx.x;
    int lane = tid & 31;
    if (tid < NEXP) cnt[tid] = 0;
    __syncthreads();
    int4 av[4];
    int ev[16];
#pragma unroll
    for (int q = 0; q < 4; q++) {
        av[q] = ((const int4*)actions)[tid + q * 256];
        ev[q * 4 + 0] = av[q].x & 7; ev[q * 4 + 1] = av[q].y & 7;
        ev[q * 4 + 2] = av[q].z & 7; ev[q * 4 + 3] = av[q].w & 7;
    }
#pragma unroll
    for (int j = 0; j < 16; j++) {
        unsigned m = __match_any_sync(0xFFFFFFFFu, ev[j]);
        if (lane == (__ffs(m) - 1)) atomicAdd(&cnt[ev[j]], __popc(m));
    }
    __syncthreads();
    if (tid == 0) {
        int s = 0;
        for (int e = 0; e < NEXP; e++) { offs[e] = s; s += cnt[e]; }
        offs[NEXP] = s;
        int nt = 0;
        for (int e = 0; e < NEXP; e++)
            for (int r = offs[e]; r < offs[e + 1]; r += BM) {
                g_tile_expert[nt] = e;
                g_tile_row0[nt]   = r;
                g_tile_rows[nt]   = min(BM, offs[e + 1] - r);
                nt++;
            }
        g_ntiles = nt;
        for (int e = 0; e < NEXP; e++) cur[e] = offs[e];
    }
    __syncthreads();
#pragma unroll
    for (int q = 0; q < 4; q++)
#pragma unroll
        for (int j = 0; j < 4; j++) {
            int i = (tid + q * 256) * 4 + j;
            int e = ev[q * 4 + j];
            unsigned m = __match_any_sync(0xFFFFFFFFu, e);
            int leader = __ffs(m) - 1;
            int rank = __popc(m & ((1u << lane) - 1u));
            int base = 0;
            if (lane == leader) base = atomicAdd(&cur[e], __popc(m));
            base = __shfl_sync(0xFFFFFFFFu, base, leader);
            g_perm[base + rank] = i;
        }
}

// ---------------------------------------------------------------------------
// Prep kernel: block 0 = sort; [1,1+NWBLK) = W hi/lo; [.., +NXBLK) = x hi/lo
// (original order, no gather); last 16 blocks = passthrough tail.
// All parts mutually independent -> sort latency fully hidden.
// ---------------------------------------------------------------------------
#define NWBLK 8192
#define NXBLK 4096
__global__ void prep_kernel(const float* __restrict__ W, const float* __restrict__ xs,
                            const int* __restrict__ mxs, const int* __restrict__ actions,
                            float* __restrict__ out, int extra) {
    if (blockIdx.x == 0) {
        sort_body(actions);
        return;
    }
    int bid = blockIdx.x - 1;
    if (bid < NWBLK) {
        size_t i = ((size_t)bid * 256 + threadIdx.x) * 4;
        float4 v = *(const float4*)(W + i);
        __nv_bfloat16 h0 = __float2bfloat16(v.x), h1 = __float2bfloat16(v.y);
        __nv_bfloat16 h2 = __float2bfloat16(v.z), h3 = __float2bfloat16(v.w);
        __nv_bfloat16 l0 = __float2bfloat16(v.x - __bfloat162float(h0));
        __nv_bfloat16 l1 = __float2bfloat16(v.y - __bfloat162float(h1));
        __nv_bfloat16 l2 = __float2bfloat16(v.z - __bfloat162float(h2));
        __nv_bfloat16 l3 = __float2bfloat16(v.w - __bfloat162float(h3));
        *(__nv_bfloat162*)(g_wh + i)     = __nv_bfloat162(h0, h1);
        *(__nv_bfloat162*)(g_wh + i + 2) = __nv_bfloat162(h2, h3);
        *(__nv_bfloat162*)(g_wl + i)     = __nv_bfloat162(l0, l1);
        *(__nv_bfloat162*)(g_wl + i + 2) = __nv_bfloat162(l2, l3);
    } else if (bid < NWBLK + NXBLK) {
        size_t i = ((size_t)(bid - NWBLK) * 256 + threadIdx.x) * 4;
        float4 v = *(const float4*)(xs + i);
        __nv_bfloat16 h0 = __float2bfloat16(v.x), h1 = __float2bfloat16(v.y);
        __nv_bfloat16 h2 = __float2bfloat16(v.z), h3 = __float2bfloat16(v.w);
        __nv_bfloat16 l0 = __float2bfloat16(v.x - __bfloat162float(h0));
        __nv_bfloat16 l1 = __float2bfloat16(v.y - __bfloat162float(h1));
        __nv_bfloat16 l2 = __float2bfloat16(v.z - __bfloat162float(h2));
        __nv_bfloat16 l3 = __float2bfloat16(v.w - __bfloat162float(h3));
        *(__nv_bfloat162*)(g_xh + i)     = __nv_bfloat162(h0, h1);
        *(__nv_bfloat162*)(g_xh + i + 2) = __nv_bfloat162(h2, h3);
        *(__nv_bfloat162*)(g_xl + i)     = __nv_bfloat162(l0, l1);
        *(__nv_bfloat162*)(g_xl + i + 2) = __nv_bfloat162(l2, l3);
    } else {
        int i = (bid - NWBLK - NXBLK) * 256 + threadIdx.x;
        if (i < B && extra > 0) {
            const size_t base = (size_t)B * DOUT;
            if (extra >= B)     out[base + i]     = (float)mxs[i];
            if (extra >= 2 * B) out[base + B + i] = (float)actions[i];
        }
    }
}

// ---------------------------------------------------------------------------
// GEMM: bf16x3 via mma.sync, 3-stage cp.async, swizzled smem.
// A rows gathered through perm at cp.async level (x stored in original order).
// 8 warps: wm = wid&3 (32-row block), wn = wid>>2 (64-col block).
// ---------------------------------------------------------------------------
__global__ __launch_bounds__(256, 2) void gemm_mma(
    const float* __restrict__ bias,
    float* __restrict__ out)
{
    int t = blockIdx.x;
    if (t >= g_ntiles) return;
    const int e     = g_tile_expert[t];
    const int row0  = g_tile_row0[t];
    const int nrows = g_tile_rows[t];
    const int n0    = blockIdx.y * BN;

    extern __shared__ __align__(128) uint8_t smem[];
    const uint32_t sb = smem_to_u32(smem);
    int*   rows_s = (int*)(smem + SMEM_ROWS);
    float* bias_s = (float*)(smem + SMEM_BIAS);

    const int tid  = threadIdx.x;
    const int wid  = tid >> 5;
    const int lane = tid & 31;
    const int wm   = wid & 3;
    const int wn   = wid >> 2;

    if (tid < BM) {
        rows_s[tid] = (tid < nrows) ? g_perm[row0 + tid] : -1;
        bias_s[tid] = bias[e * DOUT + n0 + tid];
    }
    __syncthreads();   // loaders read rows_s below

    // per-thread loader coords: 2 chunks of 16B per sub-tile
    const int cc0 = tid, cc1 = tid + 256;
    const int r0c = cc0 >> 2, c0c = cc0 & 3;
    const int r1c = cc1 >> 2, c1c = cc1 & 3;
    int gra0 = rows_s[r0c]; if (gra0 < 0) gra0 = 0;   // gather through perm
    int gra1 = rows_s[r1c]; if (gra1 < 0) gra1 = 0;
    const size_t xo0 = (size_t)gra0 * DIN + c0c * 8;
    const size_t xo1 = (size_t)gra1 * DIN + c1c * 8;
    const size_t wo0 = (size_t)(e * DOUT + n0 + r0c) * DIN + c0c * 8;
    const size_t wo1 = (size_t)(e * DOUT + n0 + r1c) * DIN + c1c * 8;
    const uint32_t d0 = SWZ(r0c, c0c);
    const uint32_t d1 = SWZ(r1c, c1c);

#define LOAD_CHUNK(ch, stg) do {                                   \
        int k0_ = (ch) * BK;                                       \
        uint32_t sB_ = sb + (stg) * STAGE_B;                       \
        cpasync16(sB_ + d0,        g_xh + xo0 + k0_);              \
        cpasync16(sB_ + d1,        g_xh + xo1 + k0_);              \
        cpasync16(sB_ + T_AL + d0, g_xl + xo0 + k0_);              \
        cpasync16(sB_ + T_AL + d1, g_xl + xo1 + k0_);              \
        cpasync16(sB_ + T_BH + d0, g_wh + wo0 + k0_);              \
        cpasync16(sB_ + T_BH + d1, g_wh + wo1 + k0_);              \
        cpasync16(sB_ + T_BL + d0, g_wl + wo0 + k0_);              \
        cpasync16(sB_ + T_BL + d1, g_wl + wo1 + k0_);              \
        CP_COMMIT();                                               \
    } while (0)

    float acc[2][8][4];
#pragma unroll
    for (int i = 0; i < 2; i++)
#pragma unroll
        for (int j = 0; j < 8; j++)
#pragma unroll
            for (int k = 0; k < 4; k++) acc[i][j][k] = 0.0f;

    // ldmatrix lane offsets, precomputed for both k-steps (swizzled)
    uint32_t aoff[2][2], boff[4][2];
#pragma unroll
    for (int mt = 0; mt < 2; mt++) {
        int r = wm * 32 + mt * 16 + (lane & 15);
#pragma unroll
        for (int ks = 0; ks < 2; ks++)
            aoff[mt][ks] = SWZ(r, ks * 2 + (lane >> 4));
    }
#pragma unroll
    for (int np = 0; np < 4; np++) {
        int nr = wn * 64 + np * 16 + (lane & 7) + ((lane >> 4) << 3);
#pragma unroll
        for (int ks = 0; ks < 2; ks++)
            boff[np][ks] = SWZ(nr, ks * 2 + ((lane >> 3) & 1));
    }

    LOAD_CHUNK(0, 0);
    LOAD_CHUNK(1, 1);
    for (int ch = 0; ch < NCHUNK; ch++) {
        int stg = ch % NSTG;
        if (ch < NCHUNK - 1) { CP_WAIT(1); } else { CP_WAIT(0); }
        __syncthreads();

        uint32_t s0 = sb + stg * STAGE_B;
#pragma unroll
        for (int ks = 0; ks < 2; ks++) {
            uint32_t ah[2][4], al[2][4], bb[4][4];
            // phase 1: ah + bh loads, then AhBh mmas
#pragma unroll
            for (int mt = 0; mt < 2; mt++)
                ldsm4(ah[mt], s0 + aoff[mt][ks]);
#pragma unroll
            for (int np = 0; np < 4; np++)
                ldsm4(bb[np], s0 + T_BH + boff[np][ks]);
#pragma unroll
            for (int mt = 0; mt < 2; mt++)
#pragma unroll
                for (int np = 0; np < 4; np++) {
                    mma16816(acc[mt][np * 2],     ah[mt], bb[np][0], bb[np][1]);
                    mma16816(acc[mt][np * 2 + 1], ah[mt], bb[np][2], bb[np][3]);
                }
            // phase 2: al loads under AhBh issue, then AlBh mmas
#pragma unroll
            for (int mt = 0; mt < 2; mt++)
                ldsm4(al[mt], s0 + T_AL + aoff[mt][ks]);
#pragma unroll
            for (int mt = 0; mt < 2; mt++)
#pragma unroll
                for (int np = 0; np < 4; np++) {
                    mma16816(acc[mt][np * 2],     al[mt], bb[np][0], bb[np][1]);
                    mma16816(acc[mt][np * 2 + 1], al[mt], bb[np][2], bb[np][3]);
                }
            // phase 3: bl loads under AlBh issue, then AhBl mmas
#pragma unroll
            for (int np = 0; np < 4; np++)
                ldsm4(bb[np], s0 + T_BL + boff[np][ks]);
#pragma unroll
            for (int mt = 0; mt < 2; mt++)
#pragma unroll
                for (int np = 0; np < 4; np++) {
                    mma16816(acc[mt][np * 2],     ah[mt], bb[np][0], bb[np][1]);
                    mma16816(acc[mt][np * 2 + 1], ah[mt], bb[np][2], bb[np][3]);
                }
        }
        // prefetch chunk ch+2 into slot (ch+2)%3
        if (ch + 2 < NCHUNK) LOAD_CHUNK(ch + 2, (ch + 2) % NSTG);
    }

    // Epilogue: scatter with bias
#pragma unroll
    for (int mt = 0; mt < 2; mt++) {
        int rbase = wm * 32 + mt * 16 + (lane >> 2);
#pragma unroll
        for (int half = 0; half < 2; half++) {
            int gr = rows_s[rbase + half * 8];
            if (gr < 0) continue;
            float* orow = out + (size_t)gr * DOUT + n0;
#pragma unroll
            for (int nt = 0; nt < 8; nt++) {
                int col = wn * 64 + nt * 8 + (lane & 3) * 2;
                float2 v;
                v.x = acc[mt][nt][half * 2 + 0] + bias_s[col];
                v.y = acc[mt][nt][half * 2 + 1] + bias_s[col + 1];
                *(float2*)(orow + col) = v;
            }
        }
    }
#undef LOAD_CHUNK
}

// ---------------------------------------------------------------------------
// Host launch
// ---------------------------------------------------------------------------
extern "C" void kernel_launch(void* const* d_in, const int* in_sizes, int n_in,
                              void* d_out, int out_size)
{
    const float* xs      = (const float*)d_in[0];
    const int*   mxs     = (const int*)d_in[1];
    const int*   actions = (const int*)d_in[2];
    const float* W       = (const float*)d_in[3];
    const float* bias    = (const float*)d_in[4];
    float*       out     = (float*)d_out;

    static bool attr_done = false;
    if (!attr_done) {
        cudaFuncSetAttribute(gemm_mma, cudaFuncAttributeMaxDynamicSharedMemorySize, SMEM_TOTAL);
        attr_done = true;
    }

    int extra = out_size - B * DOUT;

    prep_kernel<<<1 + NWBLK + NXBLK + 16, 256>>>(W, xs, mxs, actions, out, extra);

    dim3 grid(MAX_TILES, DOUT / BN);
    gemm_mma<<<grid, 256, SMEM_TOTAL>>>(bias, out);
}

// round 10
// speedup vs baseline: 4.7141x; 1.3358x over previous
#include <cuda_runtime.h>
#include <cuda_fp16.h>
#include <cstdint>

// ---------------------------------------------------------------------------
// Problem constants
// ---------------------------------------------------------------------------
#define B      4096
#define DIN    1024
#define DOUT   1024
#define NEXP   8
#define BM     128
#define BN     128
#define BK     32              // fp16 elems per k-chunk (64B rows)
#define NCHUNK (DIN / BK)      // 32
#define MAX_TILES 40
#define NSTG   4

#define TILE_B    (BM * 64)            // 8192 bytes per sub-tile (swizzled)
#define T_AL      TILE_B
#define T_BH      (2 * TILE_B)
#define STAGE_B   (3 * TILE_B)         // 24576
#define SMEM_ROWS (NSTG * STAGE_B)     // 98304
#define SMEM_BIAS (SMEM_ROWS + 512)
#define SMEM_TOTAL (SMEM_ROWS + 1024)  // 99328 -> 2 CTAs/SM

// XOR swizzle: row r (64B stride), 16B-chunk c in 0..3
#define SWZ(r, c) ((uint32_t)((r) * 64 + ((((c) ^ (((r) >> 1) & 3))) << 4)))

// ---------------------------------------------------------------------------
// Device-global scratch
// ---------------------------------------------------------------------------
__device__ int g_perm[B];
__device__ int g_tile_expert[MAX_TILES];
__device__ int g_tile_row0[MAX_TILES];
__device__ int g_tile_rows[MAX_TILES];
__device__ int g_ntiles;
__device__ __align__(128) __half g_xh[B * DIN];            // original row order
__device__ __align__(128) __half g_xl[B * DIN];
__device__ __align__(128) __half g_wh[NEXP * DOUT * DIN];

// ---------------------------------------------------------------------------
// PTX helpers (baseline sm_80+ ISA only)
// ---------------------------------------------------------------------------
__device__ __forceinline__ uint32_t smem_to_u32(const void* p) {
    uint32_t a;
    asm("{ .reg .u64 t; cvta.to.shared.u64 t, %1; cvt.u32.u64 %0, t; }" : "=r"(a) : "l"(p));
    return a;
}
__device__ __forceinline__ void cpasync16(uint32_t dst, const void* src) {
    asm volatile("cp.async.cg.shared.global [%0], [%1], 16;" :: "r"(dst), "l"(src));
}
#define CP_COMMIT() asm volatile("cp.async.commit_group;" ::: "memory")
#define CP_WAIT(n)  asm volatile("cp.async.wait_group %0;" :: "n"(n) : "memory")

__device__ __forceinline__ void ldsm4(uint32_t* r, uint32_t addr) {
    asm volatile("ldmatrix.sync.aligned.m8n8.x4.shared.b16 {%0,%1,%2,%3}, [%4];"
        : "=r"(r[0]), "=r"(r[1]), "=r"(r[2]), "=r"(r[3]) : "r"(addr));
}
__device__ __forceinline__ void mma16816(float* c, const uint32_t* a, uint32_t b0, uint32_t b1) {
    asm volatile(
        "mma.sync.aligned.m16n8k16.row.col.f32.f16.f16.f32 "
        "{%0,%1,%2,%3}, {%4,%5,%6,%7}, {%8,%9}, {%0,%1,%2,%3};"
        : "+f"(c[0]), "+f"(c[1]), "+f"(c[2]), "+f"(c[3])
        : "r"(a[0]), "r"(a[1]), "r"(a[2]), "r"(a[3]), "r"(b0), "r"(b1));
}

// ---------------------------------------------------------------------------
// Sort body (runs as block 0 of prep grid, blockDim 256 -> 16 elems/thread)
// ---------------------------------------------------------------------------
__device__ void sort_body(const int* __restrict__ actions) {
    __shared__ int cnt[NEXP];
    __shared__ int offs[NEXP + 1];
    __shared__ int cur[NEXP];
    int tid = threadIdx.x;
    int lane = tid & 31;
    if (tid < NEXP) cnt[tid] = 0;
    __syncthreads();
    int4 av[4];
    int ev[16];
#pragma unroll
    for (int q = 0; q < 4; q++) {
        av[q] = ((const int4*)actions)[tid + q * 256];
        ev[q * 4 + 0] = av[q].x & 7; ev[q * 4 + 1] = av[q].y & 7;
        ev[q * 4 + 2] = av[q].z & 7; ev[q * 4 + 3] = av[q].w & 7;
    }
#pragma unroll
    for (int j = 0; j < 16; j++) {
        unsigned m = __match_any_sync(0xFFFFFFFFu, ev[j]);
        if (lane == (__ffs(m) - 1)) atomicAdd(&cnt[ev[j]], __popc(m));
    }
    __syncthreads();
    if (tid == 0) {
        int s = 0;
        for (int e = 0; e < NEXP; e++) { offs[e] = s; s += cnt[e]; }
        offs[NEXP] = s;
        int nt = 0;
        for (int e = 0; e < NEXP; e++)
            for (int r = offs[e]; r < offs[e + 1]; r += BM) {
                g_tile_expert[nt] = e;
                g_tile_row0[nt]   = r;
                g_tile_rows[nt]   = min(BM, offs[e + 1] - r);
                nt++;
            }
        g_ntiles = nt;
        for (int e = 0; e < NEXP; e++) cur[e] = offs[e];
    }
    __syncthreads();
#pragma unroll
    for (int q = 0; q < 4; q++)
#pragma unroll
        for (int j = 0; j < 4; j++) {
            int i = (tid + q * 256) * 4 + j;
            int e = ev[q * 4 + j];
            unsigned m = __match_any_sync(0xFFFFFFFFu, e);
            int leader = __ffs(m) - 1;
            int rank = __popc(m & ((1u << lane) - 1u));
            int base = 0;
            if (lane == leader) base = atomicAdd(&cur[e], __popc(m));
            base = __shfl_sync(0xFFFFFFFFu, base, leader);
            g_perm[base + rank] = i;
        }
}

// ---------------------------------------------------------------------------
// Prep kernel: block 0 = sort; [1,1+NWBLK) = W -> fp16 hi; next NXBLK = x ->
// fp16 hi/lo (original order); last 16 blocks = passthrough tail.
// ---------------------------------------------------------------------------
#define NWBLK 8192
#define NXBLK 4096
__global__ void prep_kernel(const float* __restrict__ W, const float* __restrict__ xs,
                            const int* __restrict__ mxs, const int* __restrict__ actions,
                            float* __restrict__ out, int extra) {
    if (blockIdx.x == 0) {
        sort_body(actions);
        return;
    }
    int bid = blockIdx.x - 1;
    if (bid < NWBLK) {
        size_t i = ((size_t)bid * 256 + threadIdx.x) * 4;
        float4 v = *(const float4*)(W + i);
        __half2 h01 = __half2(__float2half(v.x), __float2half(v.y));
        __half2 h23 = __half2(__float2half(v.z), __float2half(v.w));
        *(__half2*)(g_wh + i)     = h01;
        *(__half2*)(g_wh + i + 2) = h23;
    } else if (bid < NWBLK + NXBLK) {
        size_t i = ((size_t)(bid - NWBLK) * 256 + threadIdx.x) * 4;
        float4 v = *(const float4*)(xs + i);
        __half h0 = __float2half(v.x), h1 = __float2half(v.y);
        __half h2 = __float2half(v.z), h3 = __float2half(v.w);
        __half l0 = __float2half(v.x - __half2float(h0));
        __half l1 = __float2half(v.y - __half2float(h1));
        __half l2 = __float2half(v.z - __half2float(h2));
        __half l3 = __float2half(v.w - __half2float(h3));
        *(__half2*)(g_xh + i)     = __half2(h0, h1);
        *(__half2*)(g_xh + i + 2) = __half2(h2, h3);
        *(__half2*)(g_xl + i)     = __half2(l0, l1);
        *(__half2*)(g_xl + i + 2) = __half2(l2, l3);
    } else {
        int i = (bid - NWBLK - NXBLK) * 256 + threadIdx.x;
        if (i < B && extra > 0) {
            const size_t base = (size_t)B * DOUT;
            if (extra >= B)     out[base + i]     = (float)mxs[i];
            if (extra >= 2 * B) out[base + B + i] = (float)actions[i];
        }
    }
}

// ---------------------------------------------------------------------------
// GEMM: fp16x2 via mma.sync: D = (xh + xl) @ Wh^T + bias.
// 4-stage cp.async (prefetch distance 3), swizzled smem, perm gather at load.
// 8 warps: wm = wid&3 (32-row block), wn = wid>>2 (64-col block).
// ---------------------------------------------------------------------------
__global__ __launch_bounds__(256, 2) void gemm_mma(
    const float* __restrict__ bias,
    float* __restrict__ out)
{
    int t = blockIdx.x;
    if (t >= g_ntiles) return;
    const int e     = g_tile_expert[t];
    const int row0  = g_tile_row0[t];
    const int nrows = g_tile_rows[t];
    const int n0    = blockIdx.y * BN;

    extern __shared__ __align__(128) uint8_t smem[];
    const uint32_t sb = smem_to_u32(smem);
    int*   rows_s = (int*)(smem + SMEM_ROWS);
    float* bias_s = (float*)(smem + SMEM_BIAS);

    const int tid  = threadIdx.x;
    const int wid  = tid >> 5;
    const int lane = tid & 31;
    const int wm   = wid & 3;
    const int wn   = wid >> 2;

    if (tid < BM) {
        rows_s[tid] = (tid < nrows) ? g_perm[row0 + tid] : -1;
        bias_s[tid] = bias[e * DOUT + n0 + tid];
    }
    __syncthreads();   // loaders read rows_s below

    // per-thread loader coords: 2 chunks of 16B per sub-tile
    const int cc0 = tid, cc1 = tid + 256;
    const int r0c = cc0 >> 2, c0c = cc0 & 3;
    const int r1c = cc1 >> 2, c1c = cc1 & 3;
    int gra0 = rows_s[r0c]; if (gra0 < 0) gra0 = 0;   // gather through perm
    int gra1 = rows_s[r1c]; if (gra1 < 0) gra1 = 0;
    const size_t xo0 = (size_t)gra0 * DIN + c0c * 8;
    const size_t xo1 = (size_t)gra1 * DIN + c1c * 8;
    const size_t wo0 = (size_t)(e * DOUT + n0 + r0c) * DIN + c0c * 8;
    const size_t wo1 = (size_t)(e * DOUT + n0 + r1c) * DIN + c1c * 8;
    const uint32_t d0 = SWZ(r0c, c0c);
    const uint32_t d1 = SWZ(r1c, c1c);

#define LOAD_CHUNK(ch, stg) do {                                   \
        int k0_ = (ch) * BK;                                       \
        uint32_t sB_ = sb + (stg) * STAGE_B;                       \
        cpasync16(sB_ + d0,        g_xh + xo0 + k0_);              \
        cpasync16(sB_ + d1,        g_xh + xo1 + k0_);              \
        cpasync16(sB_ + T_AL + d0, g_xl + xo0 + k0_);              \
        cpasync16(sB_ + T_AL + d1, g_xl + xo1 + k0_);              \
        cpasync16(sB_ + T_BH + d0, g_wh + wo0 + k0_);              \
        cpasync16(sB_ + T_BH + d1, g_wh + wo1 + k0_);              \
        CP_COMMIT();                                               \
    } while (0)

    float acc[2][8][4];
#pragma unroll
    for (int i = 0; i < 2; i++)
#pragma unroll
        for (int j = 0; j < 8; j++)
#pragma unroll
            for (int k = 0; k < 4; k++) acc[i][j][k] = 0.0f;

    // ldmatrix lane offsets, precomputed for both k-steps (swizzled)
    uint32_t aoff[2][2], boff[4][2];
#pragma unroll
    for (int mt = 0; mt < 2; mt++) {
        int r = wm * 32 + mt * 16 + (lane & 15);
#pragma unroll
        for (int ks = 0; ks < 2; ks++)
            aoff[mt][ks] = SWZ(r, ks * 2 + (lane >> 4));
    }
#pragma unroll
    for (int np = 0; np < 4; np++) {
        int nr = wn * 64 + np * 16 + (lane & 7) + ((lane >> 4) << 3);
#pragma unroll
        for (int ks = 0; ks < 2; ks++)
            boff[np][ks] = SWZ(nr, ks * 2 + ((lane >> 3) & 1));
    }

    LOAD_CHUNK(0, 0);
    LOAD_CHUNK(1, 1);
    LOAD_CHUNK(2, 2);
    for (int ch = 0; ch < NCHUNK; ch++) {
        int stg = ch % NSTG;
        if (ch < NCHUNK - 2)      { CP_WAIT(2); }
        else if (ch < NCHUNK - 1) { CP_WAIT(1); }
        else                      { CP_WAIT(0); }
        __syncthreads();

        uint32_t s0 = sb + stg * STAGE_B;
#pragma unroll
        for (int ks = 0; ks < 2; ks++) {
            uint32_t ah[2][4], al[2][4], bb[4][4];
            // phase 1: ah + bh loads, then AhBh mmas
#pragma unroll
            for (int mt = 0; mt < 2; mt++)
                ldsm4(ah[mt], s0 + aoff[mt][ks]);
#pragma unroll
            for (int np = 0; np < 4; np++)
                ldsm4(bb[np], s0 + T_BH + boff[np][ks]);
#pragma unroll
            for (int mt = 0; mt < 2; mt++)
#pragma unroll
                for (int np = 0; np < 4; np++) {
                    mma16816(acc[mt][np * 2],     ah[mt], bb[np][0], bb[np][1]);
                    mma16816(acc[mt][np * 2 + 1], ah[mt], bb[np][2], bb[np][3]);
                }
            // phase 2: al loads under AhBh issue, then AlBh mmas
#pragma unroll
            for (int mt = 0; mt < 2; mt++)
                ldsm4(al[mt], s0 + T_AL + aoff[mt][ks]);
#pragma unroll
            for (int mt = 0; mt < 2; mt++)
#pragma unroll
                for (int np = 0; np < 4; np++) {
                    mma16816(acc[mt][np * 2],     al[mt], bb[np][0], bb[np][1]);
                    mma16816(acc[mt][np * 2 + 1], al[mt], bb[np][2], bb[np][3]);
                }
        }
        // prefetch chunk ch+3 into slot (ch+3)%4 (consumed in iter ch-1)
        if (ch + 3 < NCHUNK) LOAD_CHUNK(ch + 3, (ch + 3) % NSTG);
    }

    // Epilogue: scatter with bias
#pragma unroll
    for (int mt = 0; mt < 2; mt++) {
        int rbase = wm * 32 + mt * 16 + (lane >> 2);
#pragma unroll
        for (int half = 0; half < 2; half++) {
            int gr = rows_s[rbase + half * 8];
            if (gr < 0) continue;
            float* orow = out + (size_t)gr * DOUT + n0;
#pragma unroll
            for (int nt = 0; nt < 8; nt++) {
                int col = wn * 64 + nt * 8 + (lane & 3) * 2;
                float2 v;
                v.x = acc[mt][nt][half * 2 + 0] + bias_s[col];
                v.y = acc[mt][nt][half * 2 + 1] + bias_s[col + 1];
                *(float2*)(orow + col) = v;
            }
        }
    }
#undef LOAD_CHUNK
}

// ---------------------------------------------------------------------------
// Host launch
// ---------------------------------------------------------------------------
extern "C" void kernel_launch(void* const* d_in, const int* in_sizes, int n_in,
                              void* d_out, int out_size)
{
    const float* xs      = (const float*)d_in[0];
    const int*   mxs     = (const int*)d_in[1];
    const int*   actions = (const int*)d_in[2];
    const float* W       = (const float*)d_in[3];
    const float* bias    = (const float*)d_in[4];
    float*       out     = (float*)d_out;

    static bool attr_done = false;
    if (!attr_done) {
        cudaFuncSetAttribute(gemm_mma, cudaFuncAttributeMaxDynamicSharedMemorySize, SMEM_TOTAL);
        attr_done = true;
    }

    int extra = out_size - B * DOUT;

    prep_kernel<<<1 + NWBLK + NXBLK + 16, 256>>>(W, xs, mxs, actions, out, extra);

    dim3 grid(MAX_TILES, DOUT / BN);
    gemm_mma<<<grid, 256, SMEM_TOTAL>>>(bias, out);
}

// round 12
// speedup vs baseline: 6.3059x; 1.3377x over previous
#include <cuda_runtime.h>
#include <cuda_fp16.h>
#include <cstdint>

// ---------------------------------------------------------------------------
// Problem constants
// ---------------------------------------------------------------------------
#define B      4096
#define DIN    1024
#define DOUT   1024
#define NEXP   8
#define BM     128
#define BN     128
#define BK     32              // fp16 elems per k-chunk (64B rows)
#define NCHUNK (DIN / BK)      // 32
#define MAX_TILES 40
#define NSTG   6

#define TILE_B    (BM * 64)            // 8192 bytes per sub-tile (swizzled)
#define T_BH      TILE_B
#define STAGE_B   (2 * TILE_B)         // 16384
#define SMEM_ROWS (NSTG * STAGE_B)     // 98304
#define SMEM_BIAS (SMEM_ROWS + 512)
#define SMEM_TOTAL (SMEM_ROWS + 1024)  // 99328 -> 2 CTAs/SM

// XOR swizzle: row r (64B stride), 16B-chunk c in 0..3
#define SWZ(r, c) ((uint32_t)((r) * 64 + ((((c) ^ (((r) >> 1) & 3))) << 4)))

// ---------------------------------------------------------------------------
// Device-global scratch
// ---------------------------------------------------------------------------
__device__ int g_perm[B];
__device__ int g_tile_expert[MAX_TILES];
__device__ int g_tile_row0[MAX_TILES];
__device__ int g_tile_rows[MAX_TILES];
__device__ int g_ntiles;
__device__ __align__(128) __half g_xh[B * DIN];            // original row order
__device__ __align__(128) __half g_wh[NEXP * DOUT * DIN];

// ---------------------------------------------------------------------------
// PTX helpers (baseline sm_80+ ISA only)
// ---------------------------------------------------------------------------
__device__ __forceinline__ uint32_t smem_to_u32(const void* p) {
    uint32_t a;
    asm("{ .reg .u64 t; cvta.to.shared.u64 t, %1; cvt.u32.u64 %0, t; }" : "=r"(a) : "l"(p));
    return a;
}
__device__ __forceinline__ void cpasync16(uint32_t dst, const void* src) {
    asm volatile("cp.async.cg.shared.global [%0], [%1], 16;" :: "r"(dst), "l"(src));
}
#define CP_COMMIT() asm volatile("cp.async.commit_group;" ::: "memory")
#define CP_WAIT(n)  asm volatile("cp.async.wait_group %0;" :: "n"(n) : "memory")

__device__ __forceinline__ void ldsm4(uint32_t* r, uint32_t addr) {
    asm volatile("ldmatrix.sync.aligned.m8n8.x4.shared.b16 {%0,%1,%2,%3}, [%4];"
        : "=r"(r[0]), "=r"(r[1]), "=r"(r[2]), "=r"(r[3]) : "r"(addr));
}
__device__ __forceinline__ void mma16816(float* c, const uint32_t* a, uint32_t b0, uint32_t b1) {
    asm volatile(
        "mma.sync.aligned.m16n8k16.row.col.f32.f16.f16.f32 "
        "{%0,%1,%2,%3}, {%4,%5,%6,%7}, {%8,%9}, {%0,%1,%2,%3};"
        : "+f"(c[0]), "+f"(c[1]), "+f"(c[2]), "+f"(c[3])
        : "r"(a[0]), "r"(a[1]), "r"(a[2]), "r"(a[3]), "r"(b0), "r"(b1));
}

// ---------------------------------------------------------------------------
// Sort body (runs as block 0 of prep grid, blockDim 256 -> 16 elems/thread)
// ---------------------------------------------------------------------------
__device__ void sort_body(const int* __restrict__ actions) {
    __shared__ int cnt[NEXP];
    __shared__ int offs[NEXP + 1];
    __shared__ int cur[NEXP];
    int tid = threadIdx.x;
    int lane = tid & 31;
    if (tid < NEXP) cnt[tid] = 0;
    __syncthreads();
    int4 av[4];
    int ev[16];
#pragma unroll
    for (int q = 0; q < 4; q++) {
        av[q] = ((const int4*)actions)[tid + q * 256];
        ev[q * 4 + 0] = av[q].x & 7; ev[q * 4 + 1] = av[q].y & 7;
        ev[q * 4 + 2] = av[q].z & 7; ev[q * 4 + 3] = av[q].w & 7;
    }
#pragma unroll
    for (int j = 0; j < 16; j++) {
        unsigned m = __match_any_sync(0xFFFFFFFFu, ev[j]);
        if (lane == (__ffs(m) - 1)) atomicAdd(&cnt[ev[j]], __popc(m));
    }
    __syncthreads();
    if (tid == 0) {
        int s = 0;
        for (int e = 0; e < NEXP; e++) { offs[e] = s; s += cnt[e]; }
        offs[NEXP] = s;
        int nt = 0;
        for (int e = 0; e < NEXP; e++)
            for (int r = offs[e]; r < offs[e + 1]; r += BM) {
                g_tile_expert[nt] = e;
                g_tile_row0[nt]   = r;
                g_tile_rows[nt]   = min(BM, offs[e + 1] - r);
                nt++;
            }
        g_ntiles = nt;
        for (int e = 0; e < NEXP; e++) cur[e] = offs[e];
    }
    __syncthreads();
#pragma unroll
    for (int q = 0; q < 4; q++)
#pragma unroll
        for (int j = 0; j < 4; j++) {
            int i = (tid + q * 256) * 4 + j;
            int e = ev[q * 4 + j];
            unsigned m = __match_any_sync(0xFFFFFFFFu, e);
            int leader = __ffs(m) - 1;
            int rank = __popc(m & ((1u << lane) - 1u));
            int base = 0;
            if (lane == leader) base = atomicAdd(&cur[e], __popc(m));
            base = __shfl_sync(0xFFFFFFFFu, base, leader);
            g_perm[base + rank] = i;
        }
}

// ---------------------------------------------------------------------------
// Prep kernel: block 0 = sort; [1,1+NWBLK) = W -> fp16; next NXBLK = x -> fp16
// (original order); last 16 blocks = passthrough tail.
// ---------------------------------------------------------------------------
#define NWBLK 8192
#define NXBLK 4096
__global__ void prep_kernel(const float* __restrict__ W, const float* __restrict__ xs,
                            const int* __restrict__ mxs, const int* __restrict__ actions,
                            float* __restrict__ out, int extra) {
    if (blockIdx.x == 0) {
        sort_body(actions);
        return;
    }
    int bid = blockIdx.x - 1;
    if (bid < NWBLK) {
        size_t i = ((size_t)bid * 256 + threadIdx.x) * 4;
        float4 v = *(const float4*)(W + i);
        *(__half2*)(g_wh + i)     = __half2(__float2half(v.x), __float2half(v.y));
        *(__half2*)(g_wh + i + 2) = __half2(__float2half(v.z), __float2half(v.w));
    } else if (bid < NWBLK + NXBLK) {
        size_t i = ((size_t)(bid - NWBLK) * 256 + threadIdx.x) * 4;
        float4 v = *(const float4*)(xs + i);
        *(__half2*)(g_xh + i)     = __half2(__float2half(v.x), __float2half(v.y));
        *(__half2*)(g_xh + i + 2) = __half2(__float2half(v.z), __float2half(v.w));
    } else {
        int i = (bid - NWBLK - NXBLK) * 256 + threadIdx.x;
        if (i < B && extra > 0) {
            const size_t base = (size_t)B * DOUT;
            if (extra >= B)     out[base + i]     = (float)mxs[i];
            if (extra >= 2 * B) out[base + B + i] = (float)actions[i];
        }
    }
}

// ---------------------------------------------------------------------------
// GEMM: fp16 single-pass via mma.sync: D = xh @ Wh^T + bias.
// 6-stage cp.async (prefetch distance 5), swizzled smem, perm gather at load.
// 8 warps: wm = wid&3 (32-row block), wn = wid>>2 (64-col block).
// ---------------------------------------------------------------------------
__global__ __launch_bounds__(256, 2) void gemm_mma(
    const float* __restrict__ bias,
    float* __restrict__ out)
{
    int t = blockIdx.x;
    if (t >= g_ntiles) return;
    const int e     = g_tile_expert[t];
    const int row0  = g_tile_row0[t];
    const int nrows = g_tile_rows[t];
    const int n0    = blockIdx.y * BN;

    extern __shared__ __align__(128) uint8_t smem[];
    const uint32_t sb = smem_to_u32(smem);
    int*   rows_s = (int*)(smem + SMEM_ROWS);
    float* bias_s = (float*)(smem + SMEM_BIAS);

    const int tid  = threadIdx.x;
    const int wid  = tid >> 5;
    const int lane = tid & 31;
    const int wm   = wid & 3;
    const int wn   = wid >> 2;

    if (tid < BM) {
        rows_s[tid] = (tid < nrows) ? g_perm[row0 + tid] : -1;
        bias_s[tid] = bias[e * DOUT + n0 + tid];
    }
    __syncthreads();   // loaders read rows_s below

    // per-thread loader coords: 2 chunks of 16B per sub-tile
    const int cc0 = tid, cc1 = tid + 256;
    const int r0c = cc0 >> 2, c0c = cc0 & 3;
    const int r1c = cc1 >> 2, c1c = cc1 & 3;
    int gra0 = rows_s[r0c]; if (gra0 < 0) gra0 = 0;   // gather through perm
    int gra1 = rows_s[r1c]; if (gra1 < 0) gra1 = 0;
    const size_t xo0 = (size_t)gra0 * DIN + c0c * 8;
    const size_t xo1 = (size_t)gra1 * DIN + c1c * 8;
    const size_t wo0 = (size_t)(e * DOUT + n0 + r0c) * DIN + c0c * 8;
    const size_t wo1 = (size_t)(e * DOUT + n0 + r1c) * DIN + c1c * 8;
    const uint32_t d0 = SWZ(r0c, c0c);
    const uint32_t d1 = SWZ(r1c, c1c);

#define LOAD_CHUNK(ch, stg) do {                                   \
        int k0_ = (ch) * BK;                                       \
        uint32_t sB_ = sb + (stg) * STAGE_B;                       \
        cpasync16(sB_ + d0,        g_xh + xo0 + k0_);              \
        cpasync16(sB_ + d1,        g_xh + xo1 + k0_);              \
        cpasync16(sB_ + T_BH + d0, g_wh + wo0 + k0_);              \
        cpasync16(sB_ + T_BH + d1, g_wh + wo1 + k0_);              \
        CP_COMMIT();                                               \
    } while (0)

    float acc[2][8][4];
#pragma unroll
    for (int i = 0; i < 2; i++)
#pragma unroll
        for (int j = 0; j < 8; j++)
#pragma unroll
            for (int k = 0; k < 4; k++) acc[i][j][k] = 0.0f;

    // ldmatrix lane offsets, precomputed for both k-steps (swizzled)
    uint32_t aoff[2][2], boff[4][2];
#pragma unroll
    for (int mt = 0; mt < 2; mt++) {
        int r = wm * 32 + mt * 16 + (lane & 15);
#pragma unroll
        for (int ks = 0; ks < 2; ks++)
            aoff[mt][ks] = SWZ(r, ks * 2 + (lane >> 4));
    }
#pragma unroll
    for (int np = 0; np < 4; np++) {
        int nr = wn * 64 + np * 16 + (lane & 7) + ((lane >> 4) << 3);
#pragma unroll
        for (int ks = 0; ks < 2; ks++)
            boff[np][ks] = SWZ(nr, ks * 2 + ((lane >> 3) & 1));
    }

    LOAD_CHUNK(0, 0);
    LOAD_CHUNK(1, 1);
    LOAD_CHUNK(2, 2);
    LOAD_CHUNK(3, 3);
    LOAD_CHUNK(4, 4);
    for (int ch = 0; ch < NCHUNK; ch++) {
        int stg = ch % NSTG;
        int ahead = NCHUNK - 1 - ch;
        if (ahead >= 5)      { CP_WAIT(4); }
        else if (ahead == 4) { CP_WAIT(4); }
        else if (ahead == 3) { CP_WAIT(3); }
        else if (ahead == 2) { CP_WAIT(2); }
        else if (ahead == 1) { CP_WAIT(1); }
        else                 { CP_WAIT(0); }
        __syncthreads();

        uint32_t s0 = sb + stg * STAGE_B;
#pragma unroll
        for (int ks = 0; ks < 2; ks++) {
            uint32_t ah[2][4], bb[4][4];
#pragma unroll
            for (int mt = 0; mt < 2; mt++)
                ldsm4(ah[mt], s0 + aoff[mt][ks]);
#pragma unroll
            for (int np = 0; np < 4; np++)
                ldsm4(bb[np], s0 + T_BH + boff[np][ks]);
#pragma unroll
            for (int mt = 0; mt < 2; mt++)
#pragma unroll
                for (int np = 0; np < 4; np++) {
                    mma16816(acc[mt][np * 2],     ah[mt], bb[np][0], bb[np][1]);
                    mma16816(acc[mt][np * 2 + 1], ah[mt], bb[np][2], bb[np][3]);
                }
        }
        // prefetch chunk ch+5 into slot (ch+5)%6 (consumed in iter ch-1)
        if (ch + 5 < NCHUNK) LOAD_CHUNK(ch + 5, (ch + 5) % NSTG);
    }

    // Epilogue: scatter with bias
#pragma unroll
    for (int mt = 0; mt < 2; mt++) {
        int rbase = wm * 32 + mt * 16 + (lane >> 2);
#pragma unroll
        for (int half = 0; half < 2; half++) {
            int gr = rows_s[rbase + half * 8];
            if (gr < 0) continue;
            float* orow = out + (size_t)gr * DOUT + n0;
#pragma unroll
            for (int nt = 0; nt < 8; nt++) {
                int col = wn * 64 + nt * 8 + (lane & 3) * 2;
                float2 v;
                v.x = acc[mt][nt][half * 2 + 0] + bias_s[col];
                v.y = acc[mt][nt][half * 2 + 1] + bias_s[col + 1];
                *(float2*)(orow + col) = v;
            }
        }
    }
#undef LOAD_CHUNK
}

// ---------------------------------------------------------------------------
// Host launch
// ---------------------------------------------------------------------------
extern "C" void kernel_launch(void* const* d_in, const int* in_sizes, int n_in,
                              void* d_out, int out_size)
{
    const float* xs      = (const float*)d_in[0];
    const int*   mxs     = (const int*)d_in[1];
    const int*   actions = (const int*)d_in[2];
    const float* W       = (const float*)d_in[3];
    const float* bias    = (const float*)d_in[4];
    float*       out     = (float*)d_out;

    static bool attr_done = false;
    if (!attr_done) {
        cudaFuncSetAttribute(gemm_mma, cudaFuncAttributeMaxDynamicSharedMemorySize, SMEM_TOTAL);
        attr_done = true;
    }

    int extra = out_size - B * DOUT;

    prep_kernel<<<1 + NWBLK + NXBLK + 16, 256>>>(W, xs, mxs, actions, out, extra);

    dim3 grid(MAX_TILES, DOUT / BN);
    gemm_mma<<<grid, 256, SMEM_TOTAL>>>(bias, out);
}

// round 14
// speedup vs baseline: 7.1597x; 1.1354x over previous
#include <cuda_runtime.h>
#include <cuda_fp16.h>
#include <cstdint>

// ---------------------------------------------------------------------------
// Problem constants
// ---------------------------------------------------------------------------
#define B      4096
#define DIN    1024
#define DOUT   1024
#define NEXP   8
#define BM     128
#define BN     128
#define BK     64              // fp16 elems per k-chunk (128B rows)
#define NCHUNK (DIN / BK)      // 16
#define MAX_TILES 40
#define NSTG   3

#define TILE_B    (BM * 128)           // 16384 bytes per sub-tile (SW128)
#define T_BH      TILE_B
#define STAGE_B   (2 * TILE_B)         // 32768
#define SMEM_ROWS (NSTG * STAGE_B)     // 98304
#define SMEM_BIAS (SMEM_ROWS + 512)
#define SMEM_TOTAL (SMEM_ROWS + 1024)  // 99328 -> 2 CTAs/SM

// SW128 XOR swizzle: row r (128B stride), 16B-chunk c in 0..7
#define SWZ(r, c) ((uint32_t)((r) * 128 + ((((c) ^ ((r) & 7))) << 4)))

// ---------------------------------------------------------------------------
// Device-global scratch
// ---------------------------------------------------------------------------
__device__ int g_perm[B];
__device__ int g_tile_expert[MAX_TILES];
__device__ int g_tile_row0[MAX_TILES];
__device__ int g_tile_rows[MAX_TILES];
__device__ int g_ntiles;
__device__ __align__(128) __half g_xh[B * DIN];            // original row order
__device__ __align__(128) __half g_wh[NEXP * DOUT * DIN];

// ---------------------------------------------------------------------------
// PTX helpers (baseline sm_80+ ISA only)
// ---------------------------------------------------------------------------
__device__ __forceinline__ uint32_t smem_to_u32(const void* p) {
    uint32_t a;
    asm("{ .reg .u64 t; cvta.to.shared.u64 t, %1; cvt.u32.u64 %0, t; }" : "=r"(a) : "l"(p));
    return a;
}
__device__ __forceinline__ void cpasync16(uint32_t dst, const void* src) {
    asm volatile("cp.async.cg.shared.global [%0], [%1], 16;" :: "r"(dst), "l"(src));
}
#define CP_COMMIT() asm volatile("cp.async.commit_group;" ::: "memory")
#define CP_WAIT(n)  asm volatile("cp.async.wait_group %0;" :: "n"(n) : "memory")

__device__ __forceinline__ void ldsm4(uint32_t* r, uint32_t addr) {
    asm volatile("ldmatrix.sync.aligned.m8n8.x4.shared.b16 {%0,%1,%2,%3}, [%4];"
        : "=r"(r[0]), "=r"(r[1]), "=r"(r[2]), "=r"(r[3]) : "r"(addr));
}
__device__ __forceinline__ void mma16816(float* c, const uint32_t* a, uint32_t b0, uint32_t b1) {
    asm volatile(
        "mma.sync.aligned.m16n8k16.row.col.f32.f16.f16.f32 "
        "{%0,%1,%2,%3}, {%4,%5,%6,%7}, {%8,%9}, {%0,%1,%2,%3};"
        : "+f"(c[0]), "+f"(c[1]), "+f"(c[2]), "+f"(c[3])
        : "r"(a[0]), "r"(a[1]), "r"(a[2]), "r"(a[3]), "r"(b0), "r"(b1));
}

// ---------------------------------------------------------------------------
// Sort body (runs as block 0 of prep grid, blockDim 256 -> 16 elems/thread)
// ---------------------------------------------------------------------------
__device__ void sort_body(const int* __restrict__ actions) {
    __shared__ int cnt[NEXP];
    __shared__ int offs[NEXP + 1];
    __shared__ int cur[NEXP];
    int tid = threadIdx.x;
    int lane = tid & 31;
    if (tid < NEXP) cnt[tid] = 0;
    __syncthreads();
    int4 av[4];
    int ev[16];
#pragma unroll
    for (int q = 0; q < 4; q++) {
        av[q] = ((const int4*)actions)[tid + q * 256];
        ev[q * 4 + 0] = av[q].x & 7; ev[q * 4 + 1] = av[q].y & 7;
        ev[q * 4 + 2] = av[q].z & 7; ev[q * 4 + 3] = av[q].w & 7;
    }
#pragma unroll
    for (int j = 0; j < 16; j++) {
        unsigned m = __match_any_sync(0xFFFFFFFFu, ev[j]);
        if (lane == (__ffs(m) - 1)) atomicAdd(&cnt[ev[j]], __popc(m));
    }
    __syncthreads();
    if (tid == 0) {
        int s = 0;
        for (int e = 0; e < NEXP; e++) { offs[e] = s; s += cnt[e]; }
        offs[NEXP] = s;
        int nt = 0;
        for (int e = 0; e < NEXP; e++)
            for (int r = offs[e]; r < offs[e + 1]; r += BM) {
                g_tile_expert[nt] = e;
                g_tile_row0[nt]   = r;
                g_tile_rows[nt]   = min(BM, offs[e + 1] - r);
                nt++;
            }
        g_ntiles = nt;
        for (int e = 0; e < NEXP; e++) cur[e] = offs[e];
    }
    __syncthreads();
#pragma unroll
    for (int q = 0; q < 4; q++)
#pragma unroll
        for (int j = 0; j < 4; j++) {
            int i = (tid + q * 256) * 4 + j;
            int e = ev[q * 4 + j];
            unsigned m = __match_any_sync(0xFFFFFFFFu, e);
            int leader = __ffs(m) - 1;
            int rank = __popc(m & ((1u << lane) - 1u));
            int base = 0;
            if (lane == leader) base = atomicAdd(&cur[e], __popc(m));
            base = __shfl_sync(0xFFFFFFFFu, base, leader);
            g_perm[base + rank] = i;
        }
}

// ---------------------------------------------------------------------------
// Prep kernel: block 0 = sort; [1,1+NWBLK) = W -> fp16; next NXBLK = x -> fp16
// (original order); last 16 blocks = passthrough tail.
// ---------------------------------------------------------------------------
#define NWBLK 8192
#define NXBLK 4096
__global__ void prep_kernel(const float* __restrict__ W, const float* __restrict__ xs,
                            const int* __restrict__ mxs, const int* __restrict__ actions,
                            float* __restrict__ out, int extra) {
    if (blockIdx.x == 0) {
        sort_body(actions);
        return;
    }
    int bid = blockIdx.x - 1;
    if (bid < NWBLK) {
        size_t i = ((size_t)bid * 256 + threadIdx.x) * 4;
        float4 v = *(const float4*)(W + i);
        *(__half2*)(g_wh + i)     = __half2(__float2half(v.x), __float2half(v.y));
        *(__half2*)(g_wh + i + 2) = __half2(__float2half(v.z), __float2half(v.w));
    } else if (bid < NWBLK + NXBLK) {
        size_t i = ((size_t)(bid - NWBLK) * 256 + threadIdx.x) * 4;
        float4 v = *(const float4*)(xs + i);
        *(__half2*)(g_xh + i)     = __half2(__float2half(v.x), __float2half(v.y));
        *(__half2*)(g_xh + i + 2) = __half2(__float2half(v.z), __float2half(v.w));
    } else {
        int i = (bid - NWBLK - NXBLK) * 256 + threadIdx.x;
        if (i < B && extra > 0) {
            const size_t base = (size_t)B * DOUT;
            if (extra >= B)     out[base + i]     = (float)mxs[i];
            if (extra >= 2 * B) out[base + B + i] = (float)actions[i];
        }
    }
}

// ---------------------------------------------------------------------------
// GEMM: fp16 via mma.sync, K=64 per stage (16 barriers total), SW128 swizzle,
// 3-stage cp.async, perm gather at load.
// 8 warps: wm = wid&3 (32-row block), wn = wid>>2 (64-col block).
// ---------------------------------------------------------------------------
__global__ __launch_bounds__(256, 2) void gemm_mma(
    const float* __restrict__ bias,
    float* __restrict__ out)
{
    int t = blockIdx.x;
    if (t >= g_ntiles) return;
    const int e     = g_tile_expert[t];
    const int row0  = g_tile_row0[t];
    const int nrows = g_tile_rows[t];
    const int n0    = blockIdx.y * BN;

    extern __shared__ __align__(128) uint8_t smem[];
    const uint32_t sb = smem_to_u32(smem);
    int*   rows_s = (int*)(smem + SMEM_ROWS);
    float* bias_s = (float*)(smem + SMEM_BIAS);

    const int tid  = threadIdx.x;
    const int wid  = tid >> 5;
    const int lane = tid & 31;
    const int wm   = wid & 3;
    const int wn   = wid >> 2;

    if (tid < BM) {
        rows_s[tid] = (tid < nrows) ? g_perm[row0 + tid] : -1;
        bias_s[tid] = bias[e * DOUT + n0 + tid];
    }
    __syncthreads();   // loaders read rows_s below

    // per-thread loader coords: 4 chunks of 16B per sub-tile (128 rows x 8 chunks)
    size_t xo[4], wo[4];
    uint32_t dsw[4];
#pragma unroll
    for (int q = 0; q < 4; q++) {
        int id = tid + q * 256;
        int rq = id >> 3, cq = id & 7;
        int gr = rows_s[rq]; if (gr < 0) gr = 0;
        xo[q]  = (size_t)gr * DIN + cq * 8;
        wo[q]  = (size_t)(e * DOUT + n0 + rq) * DIN + cq * 8;
        dsw[q] = SWZ(rq, cq);
    }

#define LOAD_CHUNK(ch, stg) do {                                   \
        int k0_ = (ch) * BK;                                       \
        uint32_t sB_ = sb + (stg) * STAGE_B;                       \
        cpasync16(sB_ + dsw[0],        g_xh + xo[0] + k0_);        \
        cpasync16(sB_ + dsw[1],        g_xh + xo[1] + k0_);        \
        cpasync16(sB_ + dsw[2],        g_xh + xo[2] + k0_);        \
        cpasync16(sB_ + dsw[3],        g_xh + xo[3] + k0_);        \
        cpasync16(sB_ + T_BH + dsw[0], g_wh + wo[0] + k0_);        \
        cpasync16(sB_ + T_BH + dsw[1], g_wh + wo[1] + k0_);        \
        cpasync16(sB_ + T_BH + dsw[2], g_wh + wo[2] + k0_);        \
        cpasync16(sB_ + T_BH + dsw[3], g_wh + wo[3] + k0_);        \
        CP_COMMIT();                                               \
    } while (0)

    float acc[2][8][4];
#pragma unroll
    for (int i = 0; i < 2; i++)
#pragma unroll
        for (int j = 0; j < 8; j++)
#pragma unroll
            for (int k = 0; k < 4; k++) acc[i][j][k] = 0.0f;

    // ldmatrix base offsets (ks=0); k-step ks applies ^ (ks<<5)
    // (SWZ(r, c0+2ks) == SWZ(r, c0) ^ (ks<<5), disjoint-bit identity)
    uint32_t aoff[2], boff[4];
#pragma unroll
    for (int mt = 0; mt < 2; mt++) {
        int r = wm * 32 + mt * 16 + (lane & 15);
        aoff[mt] = SWZ(r, (lane >> 4));
    }
#pragma unroll
    for (int np = 0; np < 4; np++) {
        int nr = wn * 64 + np * 16 + (lane & 7) + ((lane >> 4) << 3);
        boff[np] = SWZ(nr, ((lane >> 3) & 1));
    }

    LOAD_CHUNK(0, 0);
    LOAD_CHUNK(1, 1);
    for (int ch = 0; ch < NCHUNK; ch++) {
        int stg = ch % NSTG;
        if (ch < NCHUNK - 1) { CP_WAIT(1); } else { CP_WAIT(0); }
        __syncthreads();

        uint32_t s0 = sb + stg * STAGE_B;
#pragma unroll
        for (int ks = 0; ks < 4; ks++) {
            const uint32_t kx = (uint32_t)ks << 5;
            uint32_t ah[2][4], bb[4][4];
#pragma unroll
            for (int mt = 0; mt < 2; mt++)
                ldsm4(ah[mt], s0 + (aoff[mt] ^ kx));
#pragma unroll
            for (int np = 0; np < 4; np++)
                ldsm4(bb[np], s0 + T_BH + (boff[np] ^ kx));
#pragma unroll
            for (int mt = 0; mt < 2; mt++)
#pragma unroll
                for (int np = 0; np < 4; np++) {
                    mma16816(acc[mt][np * 2],     ah[mt], bb[np][0], bb[np][1]);
                    mma16816(acc[mt][np * 2 + 1], ah[mt], bb[np][2], bb[np][3]);
                }
        }
        // prefetch chunk ch+2 into slot (ch+2)%3 (consumed in iter ch-1)
        if (ch + 2 < NCHUNK) LOAD_CHUNK(ch + 2, (ch + 2) % NSTG);
    }

    // Epilogue: scatter with bias
#pragma unroll
    for (int mt = 0; mt < 2; mt++) {
        int rbase = wm * 32 + mt * 16 + (lane >> 2);
#pragma unroll
        for (int half = 0; half < 2; half++) {
            int gr = rows_s[rbase + half * 8];
            if (gr < 0) continue;
            float* orow = out + (size_t)gr * DOUT + n0;
#pragma unroll
            for (int nt = 0; nt < 8; nt++) {
                int col = wn * 64 + nt * 8 + (lane & 3) * 2;
                float2 v;
                v.x = acc[mt][nt][half * 2 + 0] + bias_s[col];
                v.y = acc[mt][nt][half * 2 + 1] + bias_s[col + 1];
                *(float2*)(orow + col) = v;
            }
        }
    }
#undef LOAD_CHUNK
}

// ---------------------------------------------------------------------------
// Host launch
// ---------------------------------------------------------------------------
extern "C" void kernel_launch(void* const* d_in, const int* in_sizes, int n_in,
                              void* d_out, int out_size)
{
    const float* xs      = (const float*)d_in[0];
    const int*   mxs     = (const int*)d_in[1];
    const int*   actions = (const int*)d_in[2];
    const float* W       = (const float*)d_in[3];
    const float* bias    = (const float*)d_in[4];
    float*       out     = (float*)d_out;

    static bool attr_done = false;
    if (!attr_done) {
        cudaFuncSetAttribute(gemm_mma, cudaFuncAttributeMaxDynamicSharedMemorySize, SMEM_TOTAL);
        attr_done = true;
    }

    int extra = out_size - B * DOUT;

    prep_kernel<<<1 + NWBLK + NXBLK + 16, 256>>>(W, xs, mxs, actions, out, extra);

    dim3 grid(MAX_TILES, DOUT / BN);
    gemm_mma<<<grid, 256, SMEM_TOTAL>>>(bias, out);
}